// round 2
// baseline (speedup 1.0000x reference)
#include <cuda_runtime.h>
#include <math.h>

// Problem constants (fixed by the reference: x [4,5,256,32,32] fp32)
#define NBL   20      // B*L
#define DD    256     // feature dim
#define NN    1024    // H*W tokens per (b,l)
#define BLK   256     // threads per CTA
#define TM    64      // query rows per CTA
#define TN    64      // kv rows per tile
#define KST   68      // padded K-tile row stride (floats): 68%32==4 -> <=2-way conflicts on V reads
#define SST   68      // padded S-tile row stride
#define NTILES (NN / TN)

#define SMEM_FLOATS (DD*TM + DD*KST + TM*SST + TM)
#define SMEM_BYTES  (SMEM_FLOATS * 4)

__global__ void __launch_bounds__(BLK, 1)
attn_fused(const float* __restrict__ x, const int* __restrict__ beta_p,
           float* __restrict__ out)
{
    const int bl = blockIdx.y;
    const int n0 = blockIdx.x * TM;
    const int t  = threadIdx.x;
    const int ti = t >> 4;   // 0..15 : S-row group / O-row group
    const int tj = t & 15;   // 0..15 : S-col group / O-d group
    const int sr = t >> 2;   // 0..63 : softmax row
    const int sq = t & 3;    // 0..3  : softmax quarter

    // beta: reference passes python int 1. Decode robustly (int bits vs float bits).
    float betaf = 1.0f;
    if (beta_p) {
        int bbits = *beta_p;
        float bf = __int_as_float(bbits);
        betaf = (fabsf(bf) >= 1e-6f && fabsf(bf) <= 1e6f) ? bf : (float)bbits;
    }

    const float* __restrict__ xb = x + (size_t)bl * DD * NN; // x[bl][d][n], n contiguous
    float* __restrict__ ob = out + (size_t)bl * NN * DD;     // out[bl][n][d], d contiguous

    extern __shared__ float sm[];
    float* Qs = sm;                 // [DD][TM]   d-major: Qs[d*TM + i]
    float* Ks = Qs + DD * TM;       // [DD][KST]  d-major: Ks[d*KST + j]  (also V)
    float* Ss = Ks + DD * KST;      // [TM][SST]  scores then P=exp(...)
    float* Al = Ss + TM * SST;      // [TM]       per-row alpha (then 1/l)

    // ---- load Q tile (coalesced float4: 16 consecutive threads span one d-row) ----
#pragma unroll
    for (int k = 0; k < (DD * TM / 4) / BLK; ++k) {
        int idx = k * BLK + t;           // 0..4095
        int d = idx >> 4, c = idx & 15;
        float4 v = *reinterpret_cast<const float4*>(xb + (size_t)d * NN + n0 + c * 4);
        *reinterpret_cast<float4*>(Qs + d * TM + c * 4) = v;
    }

    // O accumulator: rows 4*ti+r (r 0..3), cols d = 16*c + tj (c 0..15)
    float acc[4][16];
#pragma unroll
    for (int r = 0; r < 4; ++r)
#pragma unroll
        for (int c = 0; c < 16; ++c) acc[r][c] = 0.f;

    float m_run = -INFINITY;  // running max for row sr
    float l_run = 0.f;        // running sum for row sr

    for (int kt = 0; kt < NTILES; ++kt) {
        __syncthreads();  // prev GEMM2 done reading Ks/Ss before overwrite

        // ---- load KV tile (K == V here) ----
#pragma unroll
        for (int k = 0; k < (DD * TN / 4) / BLK; ++k) {
            int idx = k * BLK + t;
            int d = idx >> 4, c = idx & 15;
            float4 v = *reinterpret_cast<const float4*>(xb + (size_t)d * NN + kt * TN + c * 4);
            *reinterpret_cast<float4*>(Ks + d * KST + c * 4) = v;
        }
        __syncthreads();

        // ---- GEMM1: S[i][j] = sum_d Qs[d][i] * Ks[d][j]  (4x4 per thread) ----
        float s[4][4];
#pragma unroll
        for (int r = 0; r < 4; ++r)
#pragma unroll
            for (int c = 0; c < 4; ++c) s[r][c] = 0.f;

        const float* qp = Qs + ti * 4;
        const float* kp = Ks + tj * 4;
#pragma unroll 4
        for (int d = 0; d < DD; ++d) {
            float4 a = *reinterpret_cast<const float4*>(qp + d * TM);
            float4 b = *reinterpret_cast<const float4*>(kp + d * KST);
            s[0][0] += a.x * b.x; s[0][1] += a.x * b.y; s[0][2] += a.x * b.z; s[0][3] += a.x * b.w;
            s[1][0] += a.y * b.x; s[1][1] += a.y * b.y; s[1][2] += a.y * b.z; s[1][3] += a.y * b.w;
            s[2][0] += a.z * b.x; s[2][1] += a.z * b.y; s[2][2] += a.z * b.z; s[2][3] += a.z * b.w;
            s[3][0] += a.w * b.x; s[3][1] += a.w * b.y; s[3][2] += a.w * b.z; s[3][3] += a.w * b.w;
        }
#pragma unroll
        for (int r = 0; r < 4; ++r) {
            float4 w = make_float4(s[r][0], s[r][1], s[r][2], s[r][3]);
            *reinterpret_cast<float4*>(Ss + (ti * 4 + r) * SST + tj * 4) = w;
        }
        __syncthreads();

        // ---- online softmax: 4 threads per row, 16 cols each ----
        float* srow = Ss + sr * SST + sq * 16;
        float vals[16];
        float mx = -INFINITY;
#pragma unroll
        for (int k = 0; k < 16; ++k) { vals[k] = betaf * srow[k]; mx = fmaxf(mx, vals[k]); }
        mx = fmaxf(mx, __shfl_xor_sync(0xffffffffu, mx, 1));
        mx = fmaxf(mx, __shfl_xor_sync(0xffffffffu, mx, 2));
        float m_new = fmaxf(m_run, mx);
        float alpha = __expf(m_run - m_new);  // first tile: exp(-inf) = 0
        float ssum = 0.f;
#pragma unroll
        for (int k = 0; k < 16; ++k) {
            float p = __expf(vals[k] - m_new);
            srow[k] = p;                      // S tile becomes P tile
            ssum += p;
        }
        ssum += __shfl_xor_sync(0xffffffffu, ssum, 1);
        ssum += __shfl_xor_sync(0xffffffffu, ssum, 2);
        l_run = l_run * alpha + ssum;
        m_run = m_new;
        if (sq == 0) Al[sr] = alpha;
        __syncthreads();

        // ---- rescale O by alpha ----
        float a0 = Al[ti * 4 + 0], a1 = Al[ti * 4 + 1];
        float a2 = Al[ti * 4 + 2], a3 = Al[ti * 4 + 3];
#pragma unroll
        for (int c = 0; c < 16; ++c) {
            acc[0][c] *= a0; acc[1][c] *= a1; acc[2][c] *= a2; acc[3][c] *= a3;
        }

        // ---- GEMM2: O[i][d] += sum_j P[i][j] * V[j][d], V[j][d] = Ks[d][j] ----
#pragma unroll 2
        for (int j = 0; j < TN; ++j) {
            float p0 = Ss[(ti * 4 + 0) * SST + j];
            float p1 = Ss[(ti * 4 + 1) * SST + j];
            float p2 = Ss[(ti * 4 + 2) * SST + j];
            float p3 = Ss[(ti * 4 + 3) * SST + j];
#pragma unroll
            for (int c = 0; c < 16; ++c) {
                float v = Ks[(c * 16 + tj) * KST + j];
                acc[0][c] += p0 * v;
                acc[1][c] += p1 * v;
                acc[2][c] += p2 * v;
                acc[3][c] += p3 * v;
            }
        }
    }

    // ---- finalize: divide by l, write out ----
    __syncthreads();                 // everyone done with Al (alpha) reads
    if (sq == 0) Al[sr] = 1.f / l_run;
    __syncthreads();

    float inv[4];
#pragma unroll
    for (int r = 0; r < 4; ++r) inv[r] = Al[ti * 4 + r];
#pragma unroll
    for (int r = 0; r < 4; ++r) {
        float* orow = ob + (size_t)(n0 + ti * 4 + r) * DD;
#pragma unroll
        for (int c = 0; c < 16; ++c) {
            orow[c * 16 + tj] = acc[r][c] * inv[r];
        }
    }
}

extern "C" void kernel_launch(void* const* d_in, const int* in_sizes, int n_in,
                              void* d_out, int out_size)
{
    const float* x = (const float*)d_in[0];
    const int* beta = (n_in > 1) ? (const int*)d_in[1] : nullptr;
    float* out = (float*)d_out;

    cudaFuncSetAttribute(attn_fused, cudaFuncAttributeMaxDynamicSharedMemorySize, SMEM_BYTES);

    dim3 grid(NN / TM, NBL);  // 16 row-tiles x 20 (b,l) = 320 CTAs
    attn_fused<<<grid, BLK, SMEM_BYTES>>>(x, beta, out);
}

// round 6
// speedup vs baseline: 4.9063x; 4.9063x over previous
#include <cuda_runtime.h>
#include <cuda_bf16.h>
#include <math.h>
#include <stdint.h>

#define NBL 20
#define DD  256
#define NN  1024
#define TM  64           // query rows per CTA
#define TK  128          // kv rows per tile
#define NT  (NN/TK)      // 8
#define THREADS 256

// ---- smem layout (bytes). All row strides are 16B-granule-rotating mod 128B.
#define SM_ALPHA 0                         // 64 fp32
#define SM_INVL  256                       // 64 fp32
#define SM_Q     512                       // bf16 [256 d][72]   (64 used)
#define QSTRIDE  144
#define SM_KVH   (SM_Q + 256*QSTRIDE)      // bf16 [256 d][136]  (128 used)
#define KVSTRIDE 272
#define SM_KVL   (SM_KVH + 256*KVSTRIDE)
#define SM_S     (SM_KVL + 256*KVSTRIDE)   // fp32 [64 i][132]   (128 used)
#define SSTRIDE  528
#define SM_P     (SM_S + 64*SSTRIDE)       // bf16 [64 i][136]   (128 used)
#define PSTRIDE  272
#define SM_TOTAL (SM_P + 64*PSTRIDE)       // 227840 B

__device__ __forceinline__ uint32_t smem_u32(const void* p) {
    uint32_t a;
    asm("{ .reg .u64 t; cvta.to.shared.u64 t, %1; cvt.u32.u64 %0, t; }" : "=r"(a) : "l"(p));
    return a;
}
__device__ __forceinline__ void ldsm4(uint32_t* r, uint32_t a) {
    asm volatile("ldmatrix.sync.aligned.m8n8.x4.shared.b16 {%0,%1,%2,%3}, [%4];"
                 : "=r"(r[0]), "=r"(r[1]), "=r"(r[2]), "=r"(r[3]) : "r"(a));
}
__device__ __forceinline__ void ldsm4t(uint32_t* r, uint32_t a) {
    asm volatile("ldmatrix.sync.aligned.m8n8.x4.trans.shared.b16 {%0,%1,%2,%3}, [%4];"
                 : "=r"(r[0]), "=r"(r[1]), "=r"(r[2]), "=r"(r[3]) : "r"(a));
}
__device__ __forceinline__ void mma16816(float* d, const uint32_t* a, uint32_t b0, uint32_t b1) {
    asm volatile("mma.sync.aligned.m16n8k16.row.col.f32.bf16.bf16.f32 "
                 "{%0,%1,%2,%3},{%4,%5,%6,%7},{%8,%9},{%0,%1,%2,%3};"
                 : "+f"(d[0]), "+f"(d[1]), "+f"(d[2]), "+f"(d[3])
                 : "r"(a[0]), "r"(a[1]), "r"(a[2]), "r"(a[3]), "r"(b0), "r"(b1));
}
__device__ __forceinline__ void sts2(uint32_t a, float v0, float v1) {
    asm volatile("st.shared.v2.f32 [%0], {%1,%2};" :: "r"(a), "f"(v0), "f"(v1) : "memory");
}

__global__ void __launch_bounds__(THREADS, 1)
attn_hmma(const float* __restrict__ x, const int* __restrict__ beta_p,
          float* __restrict__ out)
{
    extern __shared__ char smem[];
    const uint32_t sb = smem_u32(smem);
    const int t = threadIdx.x, lane = t & 31, wid = t >> 5;
    const int n0 = blockIdx.x * TM;
    const int bl = blockIdx.y;
    const float* __restrict__ xb = x + (size_t)bl * DD * NN;   // x[bl][d][n]
    float* __restrict__ ob = out + (size_t)bl * NN * DD;       // out[bl][n][d]

    float betaf = 1.0f;
    if (beta_p) {
        int bbits = *beta_p;
        float bf = __int_as_float(bbits);
        betaf = (fabsf(bf) >= 1e-6f && fabsf(bf) <= 1e6f) ? bf : (float)bbits;
    }

    float* Alpha = (float*)(smem + SM_ALPHA);
    float* Invl  = (float*)(smem + SM_INVL);

    // ---- Q: fp32 [d][n0+i] -> bf16 smem [d][i] ----
#pragma unroll
    for (int it = 0; it < 16; ++it) {
        int idx = it * THREADS + t;
        int d = idx >> 4, ic = idx & 15;
        float4 v = *(const float4*)(xb + (size_t)d * NN + n0 + ic * 4);
        __nv_bfloat162 h0 = __floats2bfloat162_rn(v.x, v.y);
        __nv_bfloat162 h1 = __floats2bfloat162_rn(v.z, v.w);
        uint2 w = make_uint2(*(uint32_t*)&h0, *(uint32_t*)&h1);
        *(uint2*)(smem + SM_Q + d * QSTRIDE + ic * 8) = w;
    }

    // O accumulators: acc2[mt][nt][4]: rows 16*mt + lane/4 (+8), cols db+8*nt+2*(lane%3..)+{0,1}
    float acc2[4][4][4];
#pragma unroll
    for (int a = 0; a < 4; ++a)
#pragma unroll
        for (int b = 0; b < 4; ++b)
#pragma unroll
            for (int c = 0; c < 4; ++c) acc2[a][b][c] = 0.f;

    float m_run = -1e30f, l_run = 0.f;
    const int srow = t >> 2, sq = t & 3;
    const int mw = wid & 3, nw = wid >> 2;     // GEMM1 tiling: 4 M x 2 N
    const int i0 = mw * 16, jb = nw * 64;
    const int db = wid * 32;                   // GEMM2: warp owns 32 d-cols

    for (int kt = 0; kt < NT; ++kt) {
        __syncthreads();   // prev tile's GEMM2 done with KV/P; softmax done with S

        // ---- convert KV tile: x fp32 -> hi/lo bf16 [d][j] ----
        const int j0g = kt * TK;
#pragma unroll 4
        for (int it = 0; it < 32; ++it) {
            int idx = it * THREADS + t;
            int d = idx >> 5, jj = idx & 31;
            float4 v = *(const float4*)(xb + (size_t)d * NN + j0g + jj * 4);
            __nv_bfloat162 h0 = __floats2bfloat162_rn(v.x, v.y);
            __nv_bfloat162 h1 = __floats2bfloat162_rn(v.z, v.w);
            float lx = v.x - __bfloat162float(h0.x);
            float ly = v.y - __bfloat162float(h0.y);
            float lz = v.z - __bfloat162float(h1.x);
            float lw = v.w - __bfloat162float(h1.y);
            __nv_bfloat162 l0 = __floats2bfloat162_rn(lx, ly);
            __nv_bfloat162 l1 = __floats2bfloat162_rn(lz, lw);
            uint2 wh = make_uint2(*(uint32_t*)&h0, *(uint32_t*)&h1);
            uint2 wl = make_uint2(*(uint32_t*)&l0, *(uint32_t*)&l1);
            *(uint2*)(smem + SM_KVH + d * KVSTRIDE + jj * 8) = wh;
            *(uint2*)(smem + SM_KVL + d * KVSTRIDE + jj * 8) = wl;
        }
        __syncthreads();

        // ---- GEMM1: S[64][128] = Q @ K^T via ldmatrix.trans fragments ----
        {
            float acc1[8][4];
#pragma unroll
            for (int n = 0; n < 8; ++n)
#pragma unroll
                for (int c = 0; c < 4; ++c) acc1[n][c] = 0.f;

            const uint32_t qb = sb + SM_Q;
            const uint32_t kb = sb + SM_KVH;
#pragma unroll
            for (int k = 0; k < 16; ++k) {
                const int d0 = k * 16;
                uint32_t afr[4];
                // A (Q) trans: r = d0+(lane&7)+((lane&16)?8:0); c = i0+(lane&8)
                ldsm4t(afr, qb + (uint32_t)(d0 + (lane & 7) + ((lane >> 1) & 8)) * QSTRIDE
                              + (uint32_t)(i0 + (lane & 8)) * 2);
#pragma unroll
                for (int nt2 = 0; nt2 < 4; ++nt2) {
                    uint32_t bfr[4];
                    const int nb = jb + nt2 * 16;
                    // B (K) trans: r = d0+(lane&7)+(lane&8); c = nb+((lane&16)?8:0)
                    ldsm4t(bfr, kb + (uint32_t)(d0 + (lane & 7) + (lane & 8)) * KVSTRIDE
                                  + (uint32_t)(nb + ((lane >> 1) & 8)) * 2);
                    mma16816(acc1[2 * nt2],     afr, bfr[0], bfr[1]);
                    mma16816(acc1[2 * nt2 + 1], afr, bfr[2], bfr[3]);
                }
            }
            // write S chunk [i0..i0+15][jb..jb+63]
#pragma unroll
            for (int nt = 0; nt < 8; ++nt) {
                uint32_t a0 = sb + SM_S + (uint32_t)(i0 + (lane >> 2)) * SSTRIDE
                            + (uint32_t)(jb + nt * 8 + 2 * (lane & 3)) * 4;
                sts2(a0, acc1[nt][0], acc1[nt][1]);
                sts2(a0 + 8 * SSTRIDE, acc1[nt][2], acc1[nt][3]);
            }
        }
        __syncthreads();

        // ---- online softmax: 4 threads per row, 32 cols each ----
        {
            const float* Sp = (const float*)(smem + SM_S + srow * SSTRIDE) + sq * 32;
            float sv[32];
            float mx = -1e30f;
#pragma unroll
            for (int k = 0; k < 32; ++k) { sv[k] = betaf * Sp[k]; mx = fmaxf(mx, sv[k]); }
            mx = fmaxf(mx, __shfl_xor_sync(0xffffffffu, mx, 1));
            mx = fmaxf(mx, __shfl_xor_sync(0xffffffffu, mx, 2));
            float m_new = fmaxf(m_run, mx);
            float alpha = __expf(m_run - m_new);
            float sum = 0.f;
            char* Pp = smem + SM_P + srow * PSTRIDE + sq * 64;
#pragma unroll
            for (int kp = 0; kp < 16; ++kp) {
                float p0 = __expf(sv[2 * kp]     - m_new);
                float p1 = __expf(sv[2 * kp + 1] - m_new);
                sum += p0 + p1;
                __nv_bfloat162 pp = __floats2bfloat162_rn(p0, p1);
                *(uint32_t*)(Pp + kp * 4) = *(uint32_t*)&pp;
            }
            sum += __shfl_xor_sync(0xffffffffu, sum, 1);
            sum += __shfl_xor_sync(0xffffffffu, sum, 2);
            l_run = l_run * alpha + sum;
            m_run = m_new;
            if (sq == 0) {
                Alpha[srow] = alpha;
                if (kt == NT - 1) Invl[srow] = 1.f / l_run;
            }
        }
        __syncthreads();

        // ---- rescale O by per-row alpha ----
        if (kt > 0) {
#pragma unroll
            for (int mt = 0; mt < 4; ++mt) {
                float a0 = Alpha[16 * mt + (lane >> 2)];
                float a1 = Alpha[16 * mt + (lane >> 2) + 8];
#pragma unroll
                for (int nt = 0; nt < 4; ++nt) {
                    acc2[mt][nt][0] *= a0; acc2[mt][nt][1] *= a0;
                    acc2[mt][nt][2] *= a1; acc2[mt][nt][3] *= a1;
                }
            }
        }

        // ---- GEMM2: O += P @ (Vh + Vl); warp owns d cols [db, db+32) ----
        {
            const uint32_t pb = sb + SM_P;
            const uint32_t vh = sb + SM_KVH;
            const uint32_t vl = sb + SM_KVL;
#pragma unroll
            for (int kk = 0; kk < 8; ++kk) {
                const int j0 = kk * 16;
                uint32_t ap[4][4];
#pragma unroll
                for (int mt = 0; mt < 4; ++mt)
                    // A (P) non-trans: r = 16mt+(lane&7)+(lane&8); c = j0+((lane&16)?8:0)
                    ldsm4(ap[mt], pb + (uint32_t)(16 * mt + (lane & 7) + (lane & 8)) * PSTRIDE
                                      + (uint32_t)(j0 + ((lane >> 1) & 8)) * 2);
                uint32_t bh[2][4], blo[2][4];
#pragma unroll
                for (int h = 0; h < 2; ++h) {
                    const int d0 = db + 16 * h;
                    // B (V) non-trans: r = d0+(lane&7)+((lane&16)?8:0); c = j0+(lane&8)
                    uint32_t off = (uint32_t)(d0 + (lane & 7) + ((lane >> 1) & 8)) * KVSTRIDE
                                 + (uint32_t)(j0 + (lane & 8)) * 2;
                    ldsm4(bh[h],  vh + off);
                    ldsm4(blo[h], vl + off);
                }
#pragma unroll
                for (int mt = 0; mt < 4; ++mt)
#pragma unroll
                    for (int h = 0; h < 2; ++h) {
                        mma16816(acc2[mt][2 * h],     ap[mt], bh[h][0],  bh[h][1]);
                        mma16816(acc2[mt][2 * h + 1], ap[mt], bh[h][2],  bh[h][3]);
                        mma16816(acc2[mt][2 * h],     ap[mt], blo[h][0], blo[h][1]);
                        mma16816(acc2[mt][2 * h + 1], ap[mt], blo[h][2], blo[h][3]);
                    }
            }
        }
    }

    // ---- epilogue: normalize by 1/l and store ----
#pragma unroll
    for (int mt = 0; mt < 4; ++mt) {
        const int r0 = 16 * mt + (lane >> 2);
        const float w0 = Invl[r0];
        const float w1 = Invl[r0 + 8];
#pragma unroll
        for (int nt = 0; nt < 4; ++nt) {
            const int col = db + 8 * nt + 2 * (lane & 3);
            float2 v0 = make_float2(acc2[mt][nt][0] * w0, acc2[mt][nt][1] * w0);
            float2 v1 = make_float2(acc2[mt][nt][2] * w1, acc2[mt][nt][3] * w1);
            *(float2*)(ob + (size_t)(n0 + r0) * DD + col) = v0;
            *(float2*)(ob + (size_t)(n0 + r0 + 8) * DD + col) = v1;
        }
    }
}

extern "C" void kernel_launch(void* const* d_in, const int* in_sizes, int n_in,
                              void* d_out, int out_size)
{
    const float* x = (const float*)d_in[0];
    const int* beta = (n_in > 1) ? (const int*)d_in[1] : nullptr;
    float* out = (float*)d_out;

    cudaFuncSetAttribute(attn_hmma, cudaFuncAttributeMaxDynamicSharedMemorySize, SM_TOTAL);

    dim3 grid(NN / TM, NBL);   // 16 x 20 = 320 CTAs
    attn_hmma<<<grid, THREADS, SM_TOTAL>>>(x, beta, out);
}

// round 8
// speedup vs baseline: 5.6753x; 1.1567x over previous
#include <cuda_runtime.h>
#include <cuda_bf16.h>
#include <math.h>
#include <stdint.h>

#define NBL 20
#define DD  256
#define NN  1024
#define TM  64           // query rows per CTA
#define TK  128          // kv rows per tile
#define NT  (NN/TK)      // 8
#define THREADS 512
#define PTHRESH 1e-7f

// ---- smem layout (bytes); strides rotate 16B granules mod 128B (ldmatrix conflict-free)
#define SM_ALPHA 0                         // 64 fp32
#define SM_INVL  256                       // 64 fp32
#define SM_Q     512                       // bf16 [256 d][72]  (64 used)
#define QSTRIDE  144
#define SM_KVH   (SM_Q + 256*QSTRIDE)      // bf16 [256 d][136] (128 used)
#define KVSTRIDE 272
#define SM_KVL   (SM_KVH + 256*KVSTRIDE)
#define SM_S     (SM_KVL + 256*KVSTRIDE)   // fp32 [64 i][132]  (128 used)
#define SSTRIDE  528
#define SM_P     (SM_S + 64*SSTRIDE)       // bf16 [64 i][136]  (128 used)
#define PSTRIDE  272
#define SM_TOTAL (SM_P + 64*PSTRIDE)       // 227840 B

__device__ __forceinline__ uint32_t smem_u32(const void* p) {
    uint32_t a;
    asm("{ .reg .u64 t; cvta.to.shared.u64 t, %1; cvt.u32.u64 %0, t; }" : "=r"(a) : "l"(p));
    return a;
}
__device__ __forceinline__ void ldsm4(uint32_t* r, uint32_t a) {
    asm volatile("ldmatrix.sync.aligned.m8n8.x4.shared.b16 {%0,%1,%2,%3}, [%4];"
                 : "=r"(r[0]), "=r"(r[1]), "=r"(r[2]), "=r"(r[3]) : "r"(a));
}
__device__ __forceinline__ void ldsm4t(uint32_t* r, uint32_t a) {
    asm volatile("ldmatrix.sync.aligned.m8n8.x4.trans.shared.b16 {%0,%1,%2,%3}, [%4];"
                 : "=r"(r[0]), "=r"(r[1]), "=r"(r[2]), "=r"(r[3]) : "r"(a));
}
__device__ __forceinline__ void mma16816(float* d, const uint32_t* a, uint32_t b0, uint32_t b1) {
    asm volatile("mma.sync.aligned.m16n8k16.row.col.f32.bf16.bf16.f32 "
                 "{%0,%1,%2,%3},{%4,%5,%6,%7},{%8,%9},{%0,%1,%2,%3};"
                 : "+f"(d[0]), "+f"(d[1]), "+f"(d[2]), "+f"(d[3])
                 : "r"(a[0]), "r"(a[1]), "r"(a[2]), "r"(a[3]), "r"(b0), "r"(b1));
}
__device__ __forceinline__ void sts2(uint32_t a, float v0, float v1) {
    asm volatile("st.shared.v2.f32 [%0], {%1,%2};" :: "r"(a), "f"(v0), "f"(v1) : "memory");
}

__global__ void __launch_bounds__(THREADS, 1)
attn_hmma(const float* __restrict__ x, const int* __restrict__ beta_p,
          float* __restrict__ out)
{
    extern __shared__ char smem[];
    const uint32_t sb = smem_u32(smem);
    const int t = threadIdx.x, lane = t & 31, wid = t >> 5;
    const int n0 = blockIdx.x * TM;
    const int bl = blockIdx.y;
    const float* __restrict__ xb = x + (size_t)bl * DD * NN;   // x[bl][d][n]
    float* __restrict__ ob = out + (size_t)bl * NN * DD;       // out[bl][n][d]

    float betaf = 1.0f;
    if (beta_p) {
        int bbits = *beta_p;
        float bf = __int_as_float(bbits);
        betaf = (fabsf(bf) >= 1e-6f && fabsf(bf) <= 1e6f) ? bf : (float)bbits;
    }

    float* Alpha = (float*)(smem + SM_ALPHA);
    float* Invl  = (float*)(smem + SM_INVL);

    // ---- Q: fp32 [d][n0+i] -> bf16 smem [d][i] ----
#pragma unroll
    for (int it = 0; it < 8; ++it) {
        int idx = it * THREADS + t;
        int d = idx >> 4, ic = idx & 15;
        float4 v = *(const float4*)(xb + (size_t)d * NN + n0 + ic * 4);
        __nv_bfloat162 h0 = __floats2bfloat162_rn(v.x, v.y);
        __nv_bfloat162 h1 = __floats2bfloat162_rn(v.z, v.w);
        uint2 w = make_uint2(*(uint32_t*)&h0, *(uint32_t*)&h1);
        *(uint2*)(smem + SM_Q + d * QSTRIDE + ic * 8) = w;
    }

    // GEMM2 accumulators: warp owns 16 d-cols [db,db+16); acc2[mt][h][4]:
    // rows 16*mt + lane/4 (+8), cols db + 8*h + 2*(lane&3) + {0,1}
    float acc2[4][2][4];
#pragma unroll
    for (int a = 0; a < 4; ++a)
#pragma unroll
        for (int b = 0; b < 2; ++b)
#pragma unroll
            for (int c = 0; c < 4; ++c) acc2[a][b][c] = 0.f;

    float m_run = -1e30f, l_run = 0.f;
    const int srow = t >> 3, sq = t & 7;       // softmax: 8 threads/row, 16 cols each
    const int mw = wid & 3, nw = wid >> 2;     // GEMM1: 4 M x 4 N warp grid
    const int i0 = mw * 16, jb = nw * 32;
    const int db = wid * 16;                   // GEMM2: warp owns 16 d-cols

    for (int kt = 0; kt < NT; ++kt) {
        __syncthreads();   // prev GEMM2 done with KV/P; prev softmax done with S

        // ---- convert KV tile hi: x fp32 -> bf16 [d][j] ----
        const int j0g = kt * TK;
#pragma unroll 4
        for (int it = 0; it < 16; ++it) {
            int idx = it * THREADS + t;
            int d = idx >> 5, jj = idx & 31;
            float4 v = *(const float4*)(xb + (size_t)d * NN + j0g + jj * 4);
            __nv_bfloat162 h0 = __floats2bfloat162_rn(v.x, v.y);
            __nv_bfloat162 h1 = __floats2bfloat162_rn(v.z, v.w);
            uint2 wh = make_uint2(*(uint32_t*)&h0, *(uint32_t*)&h1);
            *(uint2*)(smem + SM_KVH + d * KVSTRIDE + jj * 8) = wh;
        }
        __syncthreads();

        // ---- GEMM1: S[64][128] = Q @ K^T; warp tile 16 x 32 ----
        {
            float acc1[4][4];
#pragma unroll
            for (int n = 0; n < 4; ++n)
#pragma unroll
                for (int c = 0; c < 4; ++c) acc1[n][c] = 0.f;

            const uint32_t qb = sb + SM_Q;
            const uint32_t kb = sb + SM_KVH;
#pragma unroll
            for (int k = 0; k < 16; ++k) {
                const int d0 = k * 16;
                uint32_t afr[4];
                ldsm4t(afr, qb + (uint32_t)(d0 + (lane & 7) + ((lane >> 1) & 8)) * QSTRIDE
                              + (uint32_t)(i0 + (lane & 8)) * 2);
#pragma unroll
                for (int h = 0; h < 2; ++h) {
                    uint32_t bfr[4];
                    const int nb = jb + h * 16;
                    ldsm4t(bfr, kb + (uint32_t)(d0 + (lane & 7) + (lane & 8)) * KVSTRIDE
                                  + (uint32_t)(nb + ((lane >> 1) & 8)) * 2);
                    mma16816(acc1[2 * h],     afr, bfr[0], bfr[1]);
                    mma16816(acc1[2 * h + 1], afr, bfr[2], bfr[3]);
                }
            }
#pragma unroll
            for (int nt = 0; nt < 4; ++nt) {
                uint32_t a0 = sb + SM_S + (uint32_t)(i0 + (lane >> 2)) * SSTRIDE
                            + (uint32_t)(jb + nt * 8 + 2 * (lane & 3)) * 4;
                sts2(a0, acc1[nt][0], acc1[nt][1]);
                sts2(a0 + 8 * SSTRIDE, acc1[nt][2], acc1[nt][3]);
            }
        }
        __syncthreads();

        // ---- online softmax (8 threads/row, 16 cols each) + skip test ----
        float pmax;
        {
            const float* Sp = (const float*)(smem + SM_S + srow * SSTRIDE) + sq * 16;
            float sv[16];
            float mx = -1e30f;
#pragma unroll
            for (int k = 0; k < 16; ++k) { sv[k] = betaf * Sp[k]; mx = fmaxf(mx, sv[k]); }
            mx = fmaxf(mx, __shfl_xor_sync(0xffffffffu, mx, 1));
            mx = fmaxf(mx, __shfl_xor_sync(0xffffffffu, mx, 2));
            mx = fmaxf(mx, __shfl_xor_sync(0xffffffffu, mx, 4));
            float m_new = fmaxf(m_run, mx);
            float alpha = __expf(m_run - m_new);
            float sum = 0.f;
            pmax = 0.f;
            char* Pp = smem + SM_P + srow * PSTRIDE + sq * 32;
#pragma unroll
            for (int kp = 0; kp < 8; ++kp) {
                float p0 = __expf(sv[2 * kp]     - m_new);
                float p1 = __expf(sv[2 * kp + 1] - m_new);
                sum += p0 + p1;
                pmax = fmaxf(pmax, fmaxf(p0, p1));
                __nv_bfloat162 pp = __floats2bfloat162_rn(p0, p1);
                *(uint32_t*)(Pp + kp * 4) = *(uint32_t*)&pp;
            }
            sum += __shfl_xor_sync(0xffffffffu, sum, 1);
            sum += __shfl_xor_sync(0xffffffffu, sum, 2);
            sum += __shfl_xor_sync(0xffffffffu, sum, 4);
            l_run = l_run * alpha + sum;
            m_run = m_new;
            if (sq == 0) {
                Alpha[srow] = alpha;
                if (kt == NT - 1) Invl[srow] = 1.f / l_run;
            }
        }
        // barrier + OR-reduce: does any p exceed the negligibility threshold?
        int need = __syncthreads_or(pmax > PTHRESH);

        // ---- rescale O by per-row alpha ----
        if (kt > 0) {
#pragma unroll
            for (int mt = 0; mt < 4; ++mt) {
                float a0 = Alpha[16 * mt + (lane >> 2)];
                float a1 = Alpha[16 * mt + (lane >> 2) + 8];
#pragma unroll
                for (int h = 0; h < 2; ++h) {
                    acc2[mt][h][0] *= a0; acc2[mt][h][1] *= a0;
                    acc2[mt][h][2] *= a1; acc2[mt][h][3] *= a1;
                }
            }
        }

        if (!need) continue;   // entire P tile negligible (< 64*128*1e-7 mass)

        // ---- lazy V_lo conversion (only for executed tiles) ----
#pragma unroll 4
        for (int it = 0; it < 16; ++it) {
            int idx = it * THREADS + t;
            int d = idx >> 5, jj = idx & 31;
            float4 v = *(const float4*)(xb + (size_t)d * NN + j0g + jj * 4);
            __nv_bfloat162 h0 = __floats2bfloat162_rn(v.x, v.y);
            __nv_bfloat162 h1 = __floats2bfloat162_rn(v.z, v.w);
            float lx = v.x - __bfloat162float(h0.x);
            float ly = v.y - __bfloat162float(h0.y);
            float lz = v.z - __bfloat162float(h1.x);
            float lw = v.w - __bfloat162float(h1.y);
            __nv_bfloat162 l0 = __floats2bfloat162_rn(lx, ly);
            __nv_bfloat162 l1 = __floats2bfloat162_rn(lz, lw);
            uint2 wl = make_uint2(*(uint32_t*)&l0, *(uint32_t*)&l1);
            *(uint2*)(smem + SM_KVL + d * KVSTRIDE + jj * 8) = wl;
        }
        __syncthreads();

        // ---- GEMM2: O += P @ (Vh + Vl); warp owns d-cols [db, db+16) ----
        {
            const uint32_t pb = sb + SM_P;
            const uint32_t vh = sb + SM_KVH;
            const uint32_t vl = sb + SM_KVL;
#pragma unroll
            for (int kk = 0; kk < 8; ++kk) {
                const int j0 = kk * 16;
                uint32_t ap[4][4];
#pragma unroll
                for (int mt = 0; mt < 4; ++mt)
                    ldsm4(ap[mt], pb + (uint32_t)(16 * mt + (lane & 7) + (lane & 8)) * PSTRIDE
                                      + (uint32_t)(j0 + ((lane >> 1) & 8)) * 2);
                uint32_t bh[4], blo[4];
                uint32_t off = (uint32_t)(db + (lane & 7) + ((lane >> 1) & 8)) * KVSTRIDE
                             + (uint32_t)(j0 + (lane & 8)) * 2;
                ldsm4(bh,  vh + off);
                ldsm4(blo, vl + off);
#pragma unroll
                for (int mt = 0; mt < 4; ++mt) {
                    mma16816(acc2[mt][0], ap[mt], bh[0],  bh[1]);
                    mma16816(acc2[mt][1], ap[mt], bh[2],  bh[3]);
                    mma16816(acc2[mt][0], ap[mt], blo[0], blo[1]);
                    mma16816(acc2[mt][1], ap[mt], blo[2], blo[3]);
                }
            }
        }
    }

    // ---- epilogue: normalize by 1/l and store ----
#pragma unroll
    for (int mt = 0; mt < 4; ++mt) {
        const int r0 = 16 * mt + (lane >> 2);
        const float w0 = Invl[r0];
        const float w1 = Invl[r0 + 8];
#pragma unroll
        for (int h = 0; h < 2; ++h) {
            const int col = db + 8 * h + 2 * (lane & 3);
            float2 v0 = make_float2(acc2[mt][h][0] * w0, acc2[mt][h][1] * w0);
            float2 v1 = make_float2(acc2[mt][h][2] * w1, acc2[mt][h][3] * w1);
            *(float2*)(ob + (size_t)(n0 + r0) * DD + col) = v0;
            *(float2*)(ob + (size_t)(n0 + r0 + 8) * DD + col) = v1;
        }
    }
}

extern "C" void kernel_launch(void* const* d_in, const int* in_sizes, int n_in,
                              void* d_out, int out_size)
{
    const float* x = (const float*)d_in[0];
    const int* beta = (n_in > 1) ? (const int*)d_in[1] : nullptr;
    float* out = (float*)d_out;

    cudaFuncSetAttribute(attn_hmma, cudaFuncAttributeMaxDynamicSharedMemorySize, SM_TOTAL);

    dim3 grid(NN / TM, NBL);   // 16 x 20 = 320 CTAs
    attn_hmma<<<grid, THREADS, SM_TOTAL>>>(x, beta, out);
}

// round 10
// speedup vs baseline: 7.3728x; 1.2991x over previous
#include <cuda_runtime.h>
#include <cuda_bf16.h>
#include <math.h>
#include <stdint.h>

#define NBL 20
#define DD  256
#define NN  1024
#define TM  64           // query rows per CTA
#define TK  128          // kv rows per tile
#define NT  (NN/TK)      // 8
#define THREADS 512
#define PTHRESH 1e-7f

// ---- smem layout (bytes); strides rotate 16B granules mod 128B (ldmatrix conflict-free)
#define SM_ALPHA 0                         // 64 fp32
#define SM_INVL  256                       // 64 fp32
#define SM_Q     512                       // bf16 [256 d][72]  (64 used)
#define QSTRIDE  144
#define SM_KVH   (SM_Q + 256*QSTRIDE)      // bf16 [256 d][136] (128 used)
#define KVSTRIDE 272
#define SM_KVL   (SM_KVH + 256*KVSTRIDE)
#define SM_S     (SM_KVL + 256*KVSTRIDE)   // fp32 [64 i][132]  (128 used)
#define SSTRIDE  528
#define SM_P     (SM_S + 64*SSTRIDE)       // bf16 [64 i][136]  (128 used)
#define PSTRIDE  272
#define SM_TOTAL (SM_P + 64*PSTRIDE)       // 227840 B

__device__ __forceinline__ uint32_t smem_u32(const void* p) {
    uint32_t a;
    asm("{ .reg .u64 t; cvta.to.shared.u64 t, %1; cvt.u32.u64 %0, t; }" : "=r"(a) : "l"(p));
    return a;
}
__device__ __forceinline__ void ldsm4(uint32_t* r, uint32_t a) {
    asm volatile("ldmatrix.sync.aligned.m8n8.x4.shared.b16 {%0,%1,%2,%3}, [%4];"
                 : "=r"(r[0]), "=r"(r[1]), "=r"(r[2]), "=r"(r[3]) : "r"(a));
}
__device__ __forceinline__ void ldsm4t(uint32_t* r, uint32_t a) {
    asm volatile("ldmatrix.sync.aligned.m8n8.x4.trans.shared.b16 {%0,%1,%2,%3}, [%4];"
                 : "=r"(r[0]), "=r"(r[1]), "=r"(r[2]), "=r"(r[3]) : "r"(a));
}
__device__ __forceinline__ void mma16816(float* d, const uint32_t* a, uint32_t b0, uint32_t b1) {
    asm volatile("mma.sync.aligned.m16n8k16.row.col.f32.bf16.bf16.f32 "
                 "{%0,%1,%2,%3},{%4,%5,%6,%7},{%8,%9},{%0,%1,%2,%3};"
                 : "+f"(d[0]), "+f"(d[1]), "+f"(d[2]), "+f"(d[3])
                 : "r"(a[0]), "r"(a[1]), "r"(a[2]), "r"(a[3]), "r"(b0), "r"(b1));
}
__device__ __forceinline__ void sts2(uint32_t a, float v0, float v1) {
    asm volatile("st.shared.v2.f32 [%0], {%1,%2};" :: "r"(a), "f"(v0), "f"(v1) : "memory");
}

__global__ void __launch_bounds__(THREADS, 1)
attn_hmma(const float* __restrict__ x, const int* __restrict__ beta_p,
          float* __restrict__ out)
{
    extern __shared__ char smem[];
    const uint32_t sb = smem_u32(smem);
    const int t = threadIdx.x, lane = t & 31, wid = t >> 5;
    const int mt = blockIdx.x;
    const int n0 = mt * TM;
    const int bl = blockIdx.y;
    const float* __restrict__ xb = x + (size_t)bl * DD * NN;   // x[bl][d][n]
    float* __restrict__ ob = out + (size_t)bl * NN * DD;       // out[bl][n][d]

    float betaf = 1.0f;
    if (beta_p) {
        int bbits = *beta_p;
        float bf = __int_as_float(bbits);
        betaf = (fabsf(bf) >= 1e-6f && fabsf(bf) <= 1e6f) ? bf : (float)bbits;
    }

    float* Alpha = (float*)(smem + SM_ALPHA);
    float* Invl  = (float*)(smem + SM_INVL);

    // ---- Q: fp32 [d][n0+i] -> bf16 smem [d][i] ----
#pragma unroll
    for (int it = 0; it < 8; ++it) {
        int idx = it * THREADS + t;
        int d = idx >> 4, ic = idx & 15;
        float4 v = *(const float4*)(xb + (size_t)d * NN + n0 + ic * 4);
        __nv_bfloat162 h0 = __floats2bfloat162_rn(v.x, v.y);
        __nv_bfloat162 h1 = __floats2bfloat162_rn(v.z, v.w);
        uint2 w = make_uint2(*(uint32_t*)&h0, *(uint32_t*)&h1);
        *(uint2*)(smem + SM_Q + d * QSTRIDE + ic * 8) = w;
    }

    // GEMM2 accumulators: warp owns 16 d-cols [db,db+16)
    float acc2[4][2][4];
#pragma unroll
    for (int a = 0; a < 4; ++a)
#pragma unroll
        for (int b = 0; b < 2; ++b)
#pragma unroll
            for (int c = 0; c < 4; ++c) acc2[a][b][c] = 0.f;

    float m_run = -1e30f, l_run = 0.f;
    const int srow = t >> 3, sq = t & 7;       // softmax: 8 threads/row, 16 cols each
    const int mw = wid & 3, nw = wid >> 2;     // GEMM1: 4 M x 4 N warp grid
    const int i0 = mw * 16, jb = nw * 32;
    const int db = wid * 16;                   // GEMM2: warp owns 16 d-cols

    // Diagonal-first tile order: the tile containing this CTA's own rows is
    // processed first, so m_run is immediately near its final value and all
    // subsequent (provably negligible) tiles skip GEMM2 + V_lo conversion.
    const int dt = mt >> 1;                    // diag block: cols [n0,n0+64) in tile mt/2

    for (int idx8 = 0; idx8 < NT; ++idx8) {
        const int kt = (idx8 == 0) ? dt : (idx8 <= dt ? idx8 - 1 : idx8);
        __syncthreads();   // prev GEMM2 done with KV/P; prev softmax done with S

        // ---- convert KV tile hi: x fp32 -> bf16 [d][j] ----
        const int j0g = kt * TK;
#pragma unroll 4
        for (int it = 0; it < 16; ++it) {
            int idx = it * THREADS + t;
            int d = idx >> 5, jj = idx & 31;
            float4 v = *(const float4*)(xb + (size_t)d * NN + j0g + jj * 4);
            __nv_bfloat162 h0 = __floats2bfloat162_rn(v.x, v.y);
            __nv_bfloat162 h1 = __floats2bfloat162_rn(v.z, v.w);
            uint2 wh = make_uint2(*(uint32_t*)&h0, *(uint32_t*)&h1);
            *(uint2*)(smem + SM_KVH + d * KVSTRIDE + jj * 8) = wh;
        }
        __syncthreads();

        // ---- GEMM1: S[64][128] = Q @ K^T; warp tile 16 x 32 ----
        {
            float acc1[4][4];
#pragma unroll
            for (int n = 0; n < 4; ++n)
#pragma unroll
                for (int c = 0; c < 4; ++c) acc1[n][c] = 0.f;

            const uint32_t qb = sb + SM_Q;
            const uint32_t kb = sb + SM_KVH;
#pragma unroll
            for (int k = 0; k < 16; ++k) {
                const int d0 = k * 16;
                uint32_t afr[4];
                ldsm4t(afr, qb + (uint32_t)(d0 + (lane & 7) + ((lane >> 1) & 8)) * QSTRIDE
                              + (uint32_t)(i0 + (lane & 8)) * 2);
#pragma unroll
                for (int h = 0; h < 2; ++h) {
                    uint32_t bfr[4];
                    const int nb = jb + h * 16;
                    ldsm4t(bfr, kb + (uint32_t)(d0 + (lane & 7) + (lane & 8)) * KVSTRIDE
                                  + (uint32_t)(nb + ((lane >> 1) & 8)) * 2);
                    mma16816(acc1[2 * h],     afr, bfr[0], bfr[1]);
                    mma16816(acc1[2 * h + 1], afr, bfr[2], bfr[3]);
                }
            }
#pragma unroll
            for (int nt = 0; nt < 4; ++nt) {
                uint32_t a0 = sb + SM_S + (uint32_t)(i0 + (lane >> 2)) * SSTRIDE
                            + (uint32_t)(jb + nt * 8 + 2 * (lane & 3)) * 4;
                sts2(a0, acc1[nt][0], acc1[nt][1]);
                sts2(a0 + 8 * SSTRIDE, acc1[nt][2], acc1[nt][3]);
            }
        }
        __syncthreads();

        // ---- online softmax (8 threads/row, 16 cols each) + skip test ----
        float pmax;
        {
            const float* Sp = (const float*)(smem + SM_S + srow * SSTRIDE) + sq * 16;
            float sv[16];
            float mx = -1e30f;
#pragma unroll
            for (int k = 0; k < 16; ++k) { sv[k] = betaf * Sp[k]; mx = fmaxf(mx, sv[k]); }
            mx = fmaxf(mx, __shfl_xor_sync(0xffffffffu, mx, 1));
            mx = fmaxf(mx, __shfl_xor_sync(0xffffffffu, mx, 2));
            mx = fmaxf(mx, __shfl_xor_sync(0xffffffffu, mx, 4));
            float m_new = fmaxf(m_run, mx);
            float alpha = __expf(m_run - m_new);
            float sum = 0.f;
            pmax = 0.f;
            char* Pp = smem + SM_P + srow * PSTRIDE + sq * 32;
#pragma unroll
            for (int kp = 0; kp < 8; ++kp) {
                float p0 = __expf(sv[2 * kp]     - m_new);
                float p1 = __expf(sv[2 * kp + 1] - m_new);
                sum += p0 + p1;
                pmax = fmaxf(pmax, fmaxf(p0, p1));
                __nv_bfloat162 pp = __floats2bfloat162_rn(p0, p1);
                *(uint32_t*)(Pp + kp * 4) = *(uint32_t*)&pp;
            }
            sum += __shfl_xor_sync(0xffffffffu, sum, 1);
            sum += __shfl_xor_sync(0xffffffffu, sum, 2);
            sum += __shfl_xor_sync(0xffffffffu, sum, 4);
            l_run = l_run * alpha + sum;
            m_run = m_new;
            if (sq == 0) {
                Alpha[srow] = alpha;
                if (idx8 == NT - 1) Invl[srow] = 1.f / l_run;
            }
        }
        // barrier + OR-reduce: does any p exceed the negligibility threshold?
        int need = __syncthreads_or(pmax > PTHRESH);

        // ---- rescale O by per-row alpha ----
        if (idx8 > 0) {
#pragma unroll
            for (int mtt = 0; mtt < 4; ++mtt) {
                float a0 = Alpha[16 * mtt + (lane >> 2)];
                float a1 = Alpha[16 * mtt + (lane >> 2) + 8];
#pragma unroll
                for (int h = 0; h < 2; ++h) {
                    acc2[mtt][h][0] *= a0; acc2[mtt][h][1] *= a0;
                    acc2[mtt][h][2] *= a1; acc2[mtt][h][3] *= a1;
                }
            }
        }

        if (!need) continue;   // entire P tile negligible (mass < 128*1e-7 per row)

        // ---- lazy V_lo conversion (only for executed tiles) ----
#pragma unroll 4
        for (int it = 0; it < 16; ++it) {
            int idx = it * THREADS + t;
            int d = idx >> 5, jj = idx & 31;
            float4 v = *(const float4*)(xb + (size_t)d * NN + j0g + jj * 4);
            __nv_bfloat162 h0 = __floats2bfloat162_rn(v.x, v.y);
            __nv_bfloat162 h1 = __floats2bfloat162_rn(v.z, v.w);
            float lx = v.x - __bfloat162float(h0.x);
            float ly = v.y - __bfloat162float(h0.y);
            float lz = v.z - __bfloat162float(h1.x);
            float lw = v.w - __bfloat162float(h1.y);
            __nv_bfloat162 l0 = __floats2bfloat162_rn(lx, ly);
            __nv_bfloat162 l1 = __floats2bfloat162_rn(lz, lw);
            uint2 wl = make_uint2(*(uint32_t*)&l0, *(uint32_t*)&l1);
            *(uint2*)(smem + SM_KVL + d * KVSTRIDE + jj * 8) = wl;
        }
        __syncthreads();

        // ---- GEMM2: O += P @ (Vh + Vl); warp owns d-cols [db, db+16) ----
        {
            const uint32_t pb = sb + SM_P;
            const uint32_t vh = sb + SM_KVH;
            const uint32_t vl = sb + SM_KVL;
#pragma unroll
            for (int kk = 0; kk < 8; ++kk) {
                const int j0 = kk * 16;
                uint32_t ap[4][4];
#pragma unroll
                for (int mtt = 0; mtt < 4; ++mtt)
                    ldsm4(ap[mtt], pb + (uint32_t)(16 * mtt + (lane & 7) + (lane & 8)) * PSTRIDE
                                       + (uint32_t)(j0 + ((lane >> 1) & 8)) * 2);
                uint32_t bh[4], blo[4];
                uint32_t off = (uint32_t)(db + (lane & 7) + ((lane >> 1) & 8)) * KVSTRIDE
                             + (uint32_t)(j0 + (lane & 8)) * 2;
                ldsm4(bh,  vh + off);
                ldsm4(blo, vl + off);
#pragma unroll
                for (int mtt = 0; mtt < 4; ++mtt) {
                    mma16816(acc2[mtt][0], ap[mtt], bh[0],  bh[1]);
                    mma16816(acc2[mtt][1], ap[mtt], bh[2],  bh[3]);
                    mma16816(acc2[mtt][0], ap[mtt], blo[0], blo[1]);
                    mma16816(acc2[mtt][1], ap[mtt], blo[2], blo[3]);
                }
            }
        }
    }

    // ---- epilogue: normalize by 1/l and store ----
#pragma unroll
    for (int mtt = 0; mtt < 4; ++mtt) {
        const int r0 = 16 * mtt + (lane >> 2);
        const float w0 = Invl[r0];
        const float w1 = Invl[r0 + 8];
#pragma unroll
        for (int h = 0; h < 2; ++h) {
            const int col = db + 8 * h + 2 * (lane & 3);
            float2 v0 = make_float2(acc2[mtt][h][0] * w0, acc2[mtt][h][1] * w0);
            float2 v1 = make_float2(acc2[mtt][h][2] * w1, acc2[mtt][h][3] * w1);
            *(float2*)(ob + (size_t)(n0 + r0) * DD + col) = v0;
            *(float2*)(ob + (size_t)(n0 + r0 + 8) * DD + col) = v1;
        }
    }
}

extern "C" void kernel_launch(void* const* d_in, const int* in_sizes, int n_in,
                              void* d_out, int out_size)
{
    const float* x = (const float*)d_in[0];
    const int* beta = (n_in > 1) ? (const int*)d_in[1] : nullptr;
    float* out = (float*)d_out;

    cudaFuncSetAttribute(attn_hmma, cudaFuncAttributeMaxDynamicSharedMemorySize, SM_TOTAL);

    dim3 grid(NN / TM, NBL);   // 16 x 20 = 320 CTAs
    attn_hmma<<<grid, THREADS, SM_TOTAL>>>(x, beta, out);
}

// round 11
// speedup vs baseline: 9.4993x; 1.2884x over previous
#include <cuda_runtime.h>
#include <cuda_bf16.h>
#include <math.h>
#include <stdint.h>

#define NBL 20
#define DD  256
#define NN  1024
#define TM  64           // query rows per CTA
#define TK  128          // kv rows per tile
#define NT  (NN/TK)      // 8
#define THREADS 512
#define LOGTHR 16.118096f   // ln(1e7): p<1e-7 <=> scaled score < m_run - LOGTHR

// Precomputed bf16 split of x: hi = bf16(x), lo = bf16(x - hi). 10.5 MB each.
#define XU4 (NBL*DD*NN/8)
__device__ uint4 g_xhi[XU4];
__device__ uint4 g_xlo[XU4];

// ---- smem layout (bytes); strides rotate 16B granules mod 128B (ldmatrix conflict-free)
#define SM_ALPHA 0                         // 64 fp32
#define SM_INVL  256                       // 64 fp32
#define SM_MX    512                       // [64][4] fp32 per-warp row maxes
#define SM_SX    1536                      // [64][4] fp32 per-warp row sums
#define SM_Q     2560                      // bf16 [256 d][72]  (64 used)
#define QSTRIDE  144
#define SM_KVH   (SM_Q + 256*QSTRIDE)      // bf16 [256 d][136] (128 used)
#define KVSTRIDE 272
#define SM_KVL   (SM_KVH + 256*KVSTRIDE)
#define SM_P     (SM_KVL + 256*KVSTRIDE)   // bf16 [64 i][136] (128 used)
#define PSTRIDE  272
#define SM_TOTAL (SM_P + 64*PSTRIDE)       // ~196 KB

__device__ __forceinline__ uint32_t smem_u32(const void* p) {
    uint32_t a;
    asm("{ .reg .u64 t; cvta.to.shared.u64 t, %1; cvt.u32.u64 %0, t; }" : "=r"(a) : "l"(p));
    return a;
}
__device__ __forceinline__ void ldsm4(uint32_t* r, uint32_t a) {
    asm volatile("ldmatrix.sync.aligned.m8n8.x4.shared.b16 {%0,%1,%2,%3}, [%4];"
                 : "=r"(r[0]), "=r"(r[1]), "=r"(r[2]), "=r"(r[3]) : "r"(a));
}
__device__ __forceinline__ void ldsm4t(uint32_t* r, uint32_t a) {
    asm volatile("ldmatrix.sync.aligned.m8n8.x4.trans.shared.b16 {%0,%1,%2,%3}, [%4];"
                 : "=r"(r[0]), "=r"(r[1]), "=r"(r[2]), "=r"(r[3]) : "r"(a));
}
__device__ __forceinline__ void mma16816(float* d, const uint32_t* a, uint32_t b0, uint32_t b1) {
    asm volatile("mma.sync.aligned.m16n8k16.row.col.f32.bf16.bf16.f32 "
                 "{%0,%1,%2,%3},{%4,%5,%6,%7},{%8,%9},{%0,%1,%2,%3};"
                 : "+f"(d[0]), "+f"(d[1]), "+f"(d[2]), "+f"(d[3])
                 : "r"(a[0]), "r"(a[1]), "r"(a[2]), "r"(a[3]), "r"(b0), "r"(b1));
}

// ---- kernel 1: split x into bf16 hi/lo ----
__global__ void __launch_bounds__(512, 2)
split_bf16(const float* __restrict__ x)
{
    int i0 = (blockIdx.x * 512 + threadIdx.x) * 4;   // float4-group index
#pragma unroll
    for (int it = 0; it < 4; ++it) {
        int i = i0 + it;                             // 0 .. 1310719
        float4 v = *((const float4*)x + i);
        __nv_bfloat162 h0 = __floats2bfloat162_rn(v.x, v.y);
        __nv_bfloat162 h1 = __floats2bfloat162_rn(v.z, v.w);
        __nv_bfloat162 l0 = __floats2bfloat162_rn(v.x - __bfloat162float(h0.x),
                                                  v.y - __bfloat162float(h0.y));
        __nv_bfloat162 l1 = __floats2bfloat162_rn(v.z - __bfloat162float(h1.x),
                                                  v.w - __bfloat162float(h1.y));
        ((uint2*)g_xhi)[i] = make_uint2(*(uint32_t*)&h0, *(uint32_t*)&h1);
        ((uint2*)g_xlo)[i] = make_uint2(*(uint32_t*)&l0, *(uint32_t*)&l1);
    }
}

__global__ void __launch_bounds__(THREADS, 1)
attn_hmma(const int* __restrict__ beta_p, float* __restrict__ out)
{
    extern __shared__ char smem[];
    const uint32_t sb = smem_u32(smem);
    const int t = threadIdx.x, lane = t & 31, wid = t >> 5;
    const int mt = blockIdx.x;
    const int n0 = mt * TM;
    const int bl = blockIdx.y;
    float* __restrict__ ob = out + (size_t)bl * NN * DD;

    float betaf = 1.0f;
    if (beta_p) {
        int bbits = *beta_p;
        float bf = __int_as_float(bbits);
        betaf = (fabsf(bf) >= 1e-6f && fabsf(bf) <= 1e6f) ? bf : (float)bbits;
    }

    float* Alpha = (float*)(smem + SM_ALPHA);
    float* Invl  = (float*)(smem + SM_INVL);
    float* Mx    = (float*)(smem + SM_MX);     // [row][nw]
    float* Sx    = (float*)(smem + SM_SX);     // [row][nw]

    const size_t eb = (size_t)bl * DD * NN;    // element base of this bl

    // ---- Q: bf16 [d][n0..n0+63] -> smem [d][i] (16B vector copies) ----
#pragma unroll
    for (int it = 0; it < 4; ++it) {
        int idx = it * THREADS + t;            // 2048 uint4
        int d = idx >> 3, ic = idx & 7;
        uint4 w = g_xhi[(eb + (size_t)d * NN + n0) / 8 + ic];
        *(uint4*)(smem + SM_Q + d * QSTRIDE + ic * 16) = w;
    }

    // GEMM2 accumulators: warp owns 16 d-cols [db,db+16)
    float acc2[4][2][4];
#pragma unroll
    for (int a = 0; a < 4; ++a)
#pragma unroll
        for (int b = 0; b < 2; ++b)
#pragma unroll
            for (int c = 0; c < 4; ++c) acc2[a][b][c] = 0.f;

    const int mw = wid & 3, nw = wid >> 2;     // GEMM1: 4 M x 4 N warp grid
    const int i0 = mw * 16, jb = nw * 32;
    const int db = wid * 16;                   // GEMM2: warp owns 16 d-cols
    const int r0 = i0 + (lane >> 2), r1 = r0 + 8;   // this thread's GEMM1 rows

    float m0 = -1e30f, m1 = -1e30f;            // running scaled max (per row, replicated)
    float l0 = 0.f, l1 = 0.f;                  // running denom

    const int dt = mt >> 1;                    // diagonal tile first

    for (int idx8 = 0; idx8 < NT; ++idx8) {
        const int kt = (idx8 == 0) ? dt : (idx8 <= dt ? idx8 - 1 : idx8);
        const int j0g = kt * TK;

        // ---- load KV-hi tile (plain 16B copies; prior readers done at last barrier) ----
#pragma unroll
        for (int it = 0; it < 8; ++it) {
            int idx = it * THREADS + t;        // 4096 uint4
            int d = idx >> 4, jj = idx & 15;
            uint4 w = g_xhi[(eb + (size_t)d * NN + j0g) / 8 + jj];
            *(uint4*)(smem + SM_KVH + d * KVSTRIDE + jj * 16) = w;
        }
        __syncthreads();

        // ---- GEMM1: S[64][128] = Q @ K^T; warp tile 16 x 32 (regs only) ----
        float acc1[4][4];
#pragma unroll
        for (int n = 0; n < 4; ++n)
#pragma unroll
            for (int c = 0; c < 4; ++c) acc1[n][c] = 0.f;
        {
            const uint32_t qb = sb + SM_Q;
            const uint32_t kb = sb + SM_KVH;
#pragma unroll
            for (int k = 0; k < 16; ++k) {
                const int d0 = k * 16;
                uint32_t afr[4];
                ldsm4t(afr, qb + (uint32_t)(d0 + (lane & 7) + ((lane >> 1) & 8)) * QSTRIDE
                              + (uint32_t)(i0 + (lane & 8)) * 2);
#pragma unroll
                for (int h = 0; h < 2; ++h) {
                    uint32_t bfr[4];
                    const int nb = jb + h * 16;
                    ldsm4t(bfr, kb + (uint32_t)(d0 + (lane & 7) + (lane & 8)) * KVSTRIDE
                                  + (uint32_t)(nb + ((lane >> 1) & 8)) * 2);
                    mma16816(acc1[2 * h],     afr, bfr[0], bfr[1]);
                    mma16816(acc1[2 * h + 1], afr, bfr[2], bfr[3]);
                }
            }
        }

        // ---- warp-partial row maxes of beta*S from fragments ----
        float wm0 = -1e30f, wm1 = -1e30f;
#pragma unroll
        for (int n = 0; n < 4; ++n) {
            wm0 = fmaxf(wm0, fmaxf(betaf * acc1[n][0], betaf * acc1[n][1]));
            wm1 = fmaxf(wm1, fmaxf(betaf * acc1[n][2], betaf * acc1[n][3]));
        }
        wm0 = fmaxf(wm0, __shfl_xor_sync(0xffffffffu, wm0, 1));
        wm0 = fmaxf(wm0, __shfl_xor_sync(0xffffffffu, wm0, 2));
        wm1 = fmaxf(wm1, __shfl_xor_sync(0xffffffffu, wm1, 1));
        wm1 = fmaxf(wm1, __shfl_xor_sync(0xffffffffu, wm1, 2));

        // skip test from maxes alone: tile contributes p<1e-7 everywhere?
        int need = __syncthreads_or((wm0 > m0 - LOGTHR) || (wm1 > m1 - LOGTHR));
        if (!need) continue;       // nothing else to do: no exp, no l/m update

        // ---- executed tile: full cross-warp max, softmax, P store ----
        if ((lane & 3) == 0) { Mx[r0 * 4 + nw] = wm0; Mx[r1 * 4 + nw] = wm1; }
        __syncthreads();
        float4 q0 = *(const float4*)(Mx + r0 * 4);
        float4 q1 = *(const float4*)(Mx + r1 * 4);
        float t0 = fmaxf(fmaxf(q0.x, q0.y), fmaxf(q0.z, q0.w));
        float t1 = fmaxf(fmaxf(q1.x, q1.y), fmaxf(q1.z, q1.w));
        float n_m0 = fmaxf(m0, t0), n_m1 = fmaxf(m1, t1);
        float al0 = __expf(m0 - n_m0), al1 = __expf(m1 - n_m1);

        float ws0 = 0.f, ws1 = 0.f;
#pragma unroll
        for (int n = 0; n < 4; ++n) {
            float p00 = __expf(betaf * acc1[n][0] - n_m0);
            float p01 = __expf(betaf * acc1[n][1] - n_m0);
            float p10 = __expf(betaf * acc1[n][2] - n_m1);
            float p11 = __expf(betaf * acc1[n][3] - n_m1);
            ws0 += p00 + p01; ws1 += p10 + p11;
            __nv_bfloat162 v0 = __floats2bfloat162_rn(p00, p01);
            __nv_bfloat162 v1 = __floats2bfloat162_rn(p10, p11);
            int col = jb + n * 8 + 2 * (lane & 3);
            *(uint32_t*)(smem + SM_P + r0 * PSTRIDE + col * 2) = *(uint32_t*)&v0;
            *(uint32_t*)(smem + SM_P + r1 * PSTRIDE + col * 2) = *(uint32_t*)&v1;
        }
        ws0 += __shfl_xor_sync(0xffffffffu, ws0, 1);
        ws0 += __shfl_xor_sync(0xffffffffu, ws0, 2);
        ws1 += __shfl_xor_sync(0xffffffffu, ws1, 1);
        ws1 += __shfl_xor_sync(0xffffffffu, ws1, 2);
        if ((lane & 3) == 0) {
            Sx[r0 * 4 + nw] = ws0; Sx[r1 * 4 + nw] = ws1;
            if (nw == 0) { Alpha[r0] = al0; Alpha[r1] = al1; }
        }

        // ---- load KV-lo tile while sums settle ----
#pragma unroll
        for (int it = 0; it < 8; ++it) {
            int idx = it * THREADS + t;
            int d = idx >> 4, jj = idx & 15;
            uint4 w = g_xlo[(eb + (size_t)d * NN + j0g) / 8 + jj];
            *(uint4*)(smem + SM_KVL + d * KVSTRIDE + jj * 16) = w;
        }
        __syncthreads();

        float4 s0 = *(const float4*)(Sx + r0 * 4);
        float4 s1 = *(const float4*)(Sx + r1 * 4);
        l0 = l0 * al0 + (s0.x + s0.y) + (s0.z + s0.w);
        l1 = l1 * al1 + (s1.x + s1.y) + (s1.z + s1.w);
        m0 = n_m0; m1 = n_m1;

        // ---- rescale O by per-row alpha (skip on first tile: O == 0) ----
        if (idx8 > 0) {
#pragma unroll
            for (int mtt = 0; mtt < 4; ++mtt) {
                float a0 = Alpha[16 * mtt + (lane >> 2)];
                float a1 = Alpha[16 * mtt + (lane >> 2) + 8];
#pragma unroll
                for (int h = 0; h < 2; ++h) {
                    acc2[mtt][h][0] *= a0; acc2[mtt][h][1] *= a0;
                    acc2[mtt][h][2] *= a1; acc2[mtt][h][3] *= a1;
                }
            }
        }

        // ---- GEMM2: O += P @ (Vh + Vl); warp owns d-cols [db, db+16) ----
        {
            const uint32_t pb = sb + SM_P;
            const uint32_t vh = sb + SM_KVH;
            const uint32_t vl = sb + SM_KVL;
#pragma unroll
            for (int kk = 0; kk < 8; ++kk) {
                const int j0 = kk * 16;
                uint32_t ap[4][4];
#pragma unroll
                for (int mtt = 0; mtt < 4; ++mtt)
                    ldsm4(ap[mtt], pb + (uint32_t)(16 * mtt + (lane & 7) + (lane & 8)) * PSTRIDE
                                       + (uint32_t)(j0 + ((lane >> 1) & 8)) * 2);
                uint32_t bh[4], blo[4];
                uint32_t off = (uint32_t)(db + (lane & 7) + ((lane >> 1) & 8)) * KVSTRIDE
                             + (uint32_t)(j0 + (lane & 8)) * 2;
                ldsm4(bh,  vh + off);
                ldsm4(blo, vl + off);
#pragma unroll
                for (int mtt = 0; mtt < 4; ++mtt) {
                    mma16816(acc2[mtt][0], ap[mtt], bh[0],  bh[1]);
                    mma16816(acc2[mtt][1], ap[mtt], bh[2],  bh[3]);
                    mma16816(acc2[mtt][0], ap[mtt], blo[0], blo[1]);
                    mma16816(acc2[mtt][1], ap[mtt], blo[2], blo[3]);
                }
            }
        }
        __syncthreads();   // protect KVH/P before next tile's stores
    }

    // ---- epilogue: publish 1/l, normalize, store ----
    if (nw == 0 && (lane & 3) == 0) { Invl[r0] = 1.f / l0; Invl[r1] = 1.f / l1; }
    __syncthreads();
#pragma unroll
    for (int mtt = 0; mtt < 4; ++mtt) {
        const int rr = 16 * mtt + (lane >> 2);
        const float w0 = Invl[rr];
        const float w1 = Invl[rr + 8];
#pragma unroll
        for (int h = 0; h < 2; ++h) {
            const int col = db + 8 * h + 2 * (lane & 3);
            float2 v0 = make_float2(acc2[mtt][h][0] * w0, acc2[mtt][h][1] * w0);
            float2 v1 = make_float2(acc2[mtt][h][2] * w1, acc2[mtt][h][3] * w1);
            *(float2*)(ob + (size_t)(n0 + rr) * DD + col) = v0;
            *(float2*)(ob + (size_t)(n0 + rr + 8) * DD + col) = v1;
        }
    }
}

extern "C" void kernel_launch(void* const* d_in, const int* in_sizes, int n_in,
                              void* d_out, int out_size)
{
    const float* x = (const float*)d_in[0];
    const int* beta = (n_in > 1) ? (const int*)d_in[1] : nullptr;
    float* out = (float*)d_out;

    split_bf16<<<XU4 / (512 * 2), 512>>>(x);   // 655360/1024 = 640 blocks

    cudaFuncSetAttribute(attn_hmma, cudaFuncAttributeMaxDynamicSharedMemorySize, SM_TOTAL);
    dim3 grid(NN / TM, NBL);   // 16 x 20 = 320 CTAs
    attn_hmma<<<grid, THREADS, SM_TOTAL>>>(beta, out);
}

// round 12
// speedup vs baseline: 9.6772x; 1.0187x over previous
#include <cuda_runtime.h>
#include <cuda_bf16.h>
#include <math.h>
#include <stdint.h>

#define NBL 20
#define DD  256
#define NN  1024
#define TM  64           // query rows per CTA
#define TK  128          // kv rows per tile
#define NT  (NN/TK)      // 8
#define THREADS 512
#define LOGTHR 16.118096f   // ln(1e7)

// Precomputed bf16 split of x: hi = bf16(x), lo = bf16(x - hi). 10.5 MB each.
#define XU4 (NBL*DD*NN/8)
__device__ uint4 g_xhi[XU4];
__device__ uint4 g_xlo[XU4];

// ---- smem layout (bytes); strides rotate 16B granules mod 128B (ldmatrix conflict-free)
#define SM_ALPHA 0                          // 64 fp32
#define SM_INVL  256                        // 64 fp32
#define SM_MX    512                        // [64][4] per-warp row maxes
#define SM_SX    1536                       // [64][4] per-warp row sums
#define SM_Q     2560                       // bf16 [256 d][72]  (64 used)
#define QSTRIDE  144
#define SM_KV0   (SM_Q + 256*QSTRIDE)       // bf16 [256 d][136] (128 used) buffer 0
#define KVSTRIDE 272
#define SM_KV1   (SM_KV0 + 256*KVSTRIDE)    // buffer 1
#define SM_P     (SM_KV1 + 256*KVSTRIDE)    // bf16 [64 i][136]  (128 used)
#define PSTRIDE  272
#define SM_TOTAL (SM_P + 64*PSTRIDE)        // 196096 B

__device__ __forceinline__ uint32_t smem_u32(const void* p) {
    uint32_t a;
    asm("{ .reg .u64 t; cvta.to.shared.u64 t, %1; cvt.u32.u64 %0, t; }" : "=r"(a) : "l"(p));
    return a;
}
__device__ __forceinline__ void ldsm4(uint32_t* r, uint32_t a) {
    asm volatile("ldmatrix.sync.aligned.m8n8.x4.shared.b16 {%0,%1,%2,%3}, [%4];"
                 : "=r"(r[0]), "=r"(r[1]), "=r"(r[2]), "=r"(r[3]) : "r"(a));
}
__device__ __forceinline__ void ldsm4t(uint32_t* r, uint32_t a) {
    asm volatile("ldmatrix.sync.aligned.m8n8.x4.trans.shared.b16 {%0,%1,%2,%3}, [%4];"
                 : "=r"(r[0]), "=r"(r[1]), "=r"(r[2]), "=r"(r[3]) : "r"(a));
}
__device__ __forceinline__ void mma16816(float* d, const uint32_t* a, uint32_t b0, uint32_t b1) {
    asm volatile("mma.sync.aligned.m16n8k16.row.col.f32.bf16.bf16.f32 "
                 "{%0,%1,%2,%3},{%4,%5,%6,%7},{%8,%9},{%0,%1,%2,%3};"
                 : "+f"(d[0]), "+f"(d[1]), "+f"(d[2]), "+f"(d[3])
                 : "r"(a[0]), "r"(a[1]), "r"(a[2]), "r"(a[3]), "r"(b0), "r"(b1));
}
__device__ __forceinline__ void cp_async16(uint32_t saddr, const void* gaddr) {
    asm volatile("cp.async.cg.shared.global [%0], [%1], 16;" :: "r"(saddr), "l"(gaddr) : "memory");
}
#define CP_COMMIT() asm volatile("cp.async.commit_group;" ::: "memory")
#define CP_WAIT0()  asm volatile("cp.async.wait_group 0;" ::: "memory")

// ---- kernel 1: split x into bf16 hi/lo ----
__global__ void __launch_bounds__(512, 2)
split_bf16(const float* __restrict__ x)
{
    int i0 = (blockIdx.x * 512 + threadIdx.x) * 4;
#pragma unroll
    for (int it = 0; it < 4; ++it) {
        int i = i0 + it;
        float4 v = *((const float4*)x + i);
        __nv_bfloat162 h0 = __floats2bfloat162_rn(v.x, v.y);
        __nv_bfloat162 h1 = __floats2bfloat162_rn(v.z, v.w);
        __nv_bfloat162 l0 = __floats2bfloat162_rn(v.x - __bfloat162float(h0.x),
                                                  v.y - __bfloat162float(h0.y));
        __nv_bfloat162 l1 = __floats2bfloat162_rn(v.z - __bfloat162float(h1.x),
                                                  v.w - __bfloat162float(h1.y));
        ((uint2*)g_xhi)[i] = make_uint2(*(uint32_t*)&h0, *(uint32_t*)&h1);
        ((uint2*)g_xlo)[i] = make_uint2(*(uint32_t*)&l0, *(uint32_t*)&l1);
    }
}

__global__ void __launch_bounds__(THREADS, 1)
attn_hmma(const int* __restrict__ beta_p, float* __restrict__ out)
{
    extern __shared__ char smem[];
    const uint32_t sb = smem_u32(smem);
    const int t = threadIdx.x, lane = t & 31, wid = t >> 5;
    const int mt = blockIdx.x;
    const int n0 = mt * TM;
    const int bl = blockIdx.y;
    float* __restrict__ ob = out + (size_t)bl * NN * DD;

    float betaf = 1.0f;
    if (beta_p) {
        int bbits = *beta_p;
        float bf = __int_as_float(bbits);
        betaf = (fabsf(bf) >= 1e-6f && fabsf(bf) <= 1e6f) ? bf : (float)bbits;
    }

    float* Alpha = (float*)(smem + SM_ALPHA);
    float* Invl  = (float*)(smem + SM_INVL);
    float* Mx    = (float*)(smem + SM_MX);
    float* Sx    = (float*)(smem + SM_SX);

    const size_t eb = (size_t)bl * DD * NN;
    const int ld_d = t >> 4, ld_j = t & 15;     // this thread's KV copy slice base

    const int dt = mt >> 1;                     // diagonal tile first
    // tile order: dt, then 0..NT-1 skipping dt
    // kt(idx8) = idx8==0 ? dt : (idx8<=dt ? idx8-1 : idx8)

    // ---- prefetch tile order[0] into buffer 0 via cp.async ----
    {
        const int j0g = dt * TK;
#pragma unroll
        for (int it = 0; it < 8; ++it) {
            int d = ld_d + it * 32;
            cp_async16(sb + SM_KV0 + d * KVSTRIDE + ld_j * 16,
                       &g_xhi[(eb + (size_t)d * NN + j0g) / 8 + ld_j]);
        }
        CP_COMMIT();
    }

    // ---- Q: bf16 [d][n0..n0+63] -> smem [d][i] ----
#pragma unroll
    for (int it = 0; it < 4; ++it) {
        int idx = it * THREADS + t;
        int d = idx >> 3, ic = idx & 7;
        uint4 w = g_xhi[(eb + (size_t)d * NN + n0) / 8 + ic];
        *(uint4*)(smem + SM_Q + d * QSTRIDE + ic * 16) = w;
    }

    float acc2[4][2][4];
#pragma unroll
    for (int a = 0; a < 4; ++a)
#pragma unroll
        for (int b = 0; b < 2; ++b)
#pragma unroll
            for (int c = 0; c < 4; ++c) acc2[a][b][c] = 0.f;

    const int mw = wid & 3, nw = wid >> 2;
    const int i0 = mw * 16, jb = nw * 32;
    const int db = wid * 16;
    const int r0 = i0 + (lane >> 2), r1 = r0 + 8;

    float m0 = -1e30f, m1 = -1e30f;
    float l0 = 0.f, l1 = 0.f;

    for (int idx8 = 0; idx8 < NT; ++idx8) {
        const int cur = (idx8 & 1) ? SM_KV1 : SM_KV0;
        const int nxt = (idx8 & 1) ? SM_KV0 : SM_KV1;

        CP_WAIT0();           // current tile's async copies landed (this thread)
        __syncthreads();      // ... and everyone else's; prior readers of `nxt` done

        // ---- issue prefetch of the next tile into the other buffer ----
        if (idx8 + 1 < NT) {
            const int ktn = (idx8 + 1 <= dt) ? idx8 : idx8 + 1;
            const int j0n = ktn * TK;
#pragma unroll
            for (int it = 0; it < 8; ++it) {
                int d = ld_d + it * 32;
                cp_async16(sb + nxt + d * KVSTRIDE + ld_j * 16,
                           &g_xhi[(eb + (size_t)d * NN + j0n) / 8 + ld_j]);
            }
            CP_COMMIT();
        }

        // ---- GEMM1: S[64][128] = Q @ K^T; warp tile 16 x 32 (regs only) ----
        float acc1[4][4];
#pragma unroll
        for (int n = 0; n < 4; ++n)
#pragma unroll
            for (int c = 0; c < 4; ++c) acc1[n][c] = 0.f;
        {
            const uint32_t qb = sb + SM_Q;
            const uint32_t kb = sb + cur;
#pragma unroll
            for (int k = 0; k < 16; ++k) {
                const int d0 = k * 16;
                uint32_t afr[4];
                ldsm4t(afr, qb + (uint32_t)(d0 + (lane & 7) + ((lane >> 1) & 8)) * QSTRIDE
                              + (uint32_t)(i0 + (lane & 8)) * 2);
#pragma unroll
                for (int h = 0; h < 2; ++h) {
                    uint32_t bfr[4];
                    const int nb = jb + h * 16;
                    ldsm4t(bfr, kb + (uint32_t)(d0 + (lane & 7) + (lane & 8)) * KVSTRIDE
                                  + (uint32_t)(nb + ((lane >> 1) & 8)) * 2);
                    mma16816(acc1[2 * h],     afr, bfr[0], bfr[1]);
                    mma16816(acc1[2 * h + 1], afr, bfr[2], bfr[3]);
                }
            }
        }

        // ---- warp-partial row maxes of beta*S ----
        float wm0 = -1e30f, wm1 = -1e30f;
#pragma unroll
        for (int n = 0; n < 4; ++n) {
            wm0 = fmaxf(wm0, fmaxf(betaf * acc1[n][0], betaf * acc1[n][1]));
            wm1 = fmaxf(wm1, fmaxf(betaf * acc1[n][2], betaf * acc1[n][3]));
        }
        wm0 = fmaxf(wm0, __shfl_xor_sync(0xffffffffu, wm0, 1));
        wm0 = fmaxf(wm0, __shfl_xor_sync(0xffffffffu, wm0, 2));
        wm1 = fmaxf(wm1, __shfl_xor_sync(0xffffffffu, wm1, 1));
        wm1 = fmaxf(wm1, __shfl_xor_sync(0xffffffffu, wm1, 2));

        int need = __syncthreads_or((wm0 > m0 - LOGTHR) || (wm1 > m1 - LOGTHR));
        if (!need) continue;   // tile certified negligible (all p < 1e-7)

        // ---- executed tile: cross-warp max ----
        if ((lane & 3) == 0) { Mx[r0 * 4 + nw] = wm0; Mx[r1 * 4 + nw] = wm1; }
        __syncthreads();
        float4 q0 = *(const float4*)(Mx + r0 * 4);
        float4 q1 = *(const float4*)(Mx + r1 * 4);
        float t0 = fmaxf(fmaxf(q0.x, q0.y), fmaxf(q0.z, q0.w));
        float t1 = fmaxf(fmaxf(q1.x, q1.y), fmaxf(q1.z, q1.w));
        float n_m0 = fmaxf(m0, t0), n_m1 = fmaxf(m1, t1);
        float al0 = __expf(m0 - n_m0), al1 = __expf(m1 - n_m1);

        float ws0 = 0.f, ws1 = 0.f;
#pragma unroll
        for (int n = 0; n < 4; ++n) {
            float p00 = __expf(betaf * acc1[n][0] - n_m0);
            float p01 = __expf(betaf * acc1[n][1] - n_m0);
            float p10 = __expf(betaf * acc1[n][2] - n_m1);
            float p11 = __expf(betaf * acc1[n][3] - n_m1);
            ws0 += p00 + p01; ws1 += p10 + p11;
            __nv_bfloat162 v0 = __floats2bfloat162_rn(p00, p01);
            __nv_bfloat162 v1 = __floats2bfloat162_rn(p10, p11);
            int col = jb + n * 8 + 2 * (lane & 3);
            *(uint32_t*)(smem + SM_P + r0 * PSTRIDE + col * 2) = *(uint32_t*)&v0;
            *(uint32_t*)(smem + SM_P + r1 * PSTRIDE + col * 2) = *(uint32_t*)&v1;
        }
        ws0 += __shfl_xor_sync(0xffffffffu, ws0, 1);
        ws0 += __shfl_xor_sync(0xffffffffu, ws0, 2);
        ws1 += __shfl_xor_sync(0xffffffffu, ws1, 1);
        ws1 += __shfl_xor_sync(0xffffffffu, ws1, 2);
        if ((lane & 3) == 0) {
            Sx[r0 * 4 + nw] = ws0; Sx[r1 * 4 + nw] = ws1;
            if (nw == 0) { Alpha[r0] = al0; Alpha[r1] = al1; }
        }
        __syncthreads();   // P, Sx, Alpha visible

        float4 s0 = *(const float4*)(Sx + r0 * 4);
        float4 s1 = *(const float4*)(Sx + r1 * 4);
        l0 = l0 * al0 + (s0.x + s0.y) + (s0.z + s0.w);
        l1 = l1 * al1 + (s1.x + s1.y) + (s1.z + s1.w);
        m0 = n_m0; m1 = n_m1;

        if (idx8 > 0) {
#pragma unroll
            for (int mtt = 0; mtt < 4; ++mtt) {
                float a0 = Alpha[16 * mtt + (lane >> 2)];
                float a1 = Alpha[16 * mtt + (lane >> 2) + 8];
#pragma unroll
                for (int h = 0; h < 2; ++h) {
                    acc2[mtt][h][0] *= a0; acc2[mtt][h][1] *= a0;
                    acc2[mtt][h][2] *= a1; acc2[mtt][h][3] *= a1;
                }
            }
        }

        // ---- GEMM2 pass A: O += P @ V_hi (from cur buffer) ----
        const int j0g = ((idx8 == 0) ? dt : (idx8 <= dt ? idx8 - 1 : idx8)) * TK;
        const uint32_t pb = sb + SM_P;
#pragma unroll
        for (int kk = 0; kk < 8; ++kk) {
            const int j0 = kk * 16;
            uint32_t ap[4][4];
#pragma unroll
            for (int mtt = 0; mtt < 4; ++mtt)
                ldsm4(ap[mtt], pb + (uint32_t)(16 * mtt + (lane & 7) + (lane & 8)) * PSTRIDE
                                   + (uint32_t)(j0 + ((lane >> 1) & 8)) * 2);
            uint32_t bh[4];
            uint32_t off = (uint32_t)(db + (lane & 7) + ((lane >> 1) & 8)) * KVSTRIDE
                         + (uint32_t)(j0 + (lane & 8)) * 2;
            ldsm4(bh, sb + cur + off);
#pragma unroll
            for (int mtt = 0; mtt < 4; ++mtt) {
                mma16816(acc2[mtt][0], ap[mtt], bh[0], bh[1]);
                mma16816(acc2[mtt][1], ap[mtt], bh[2], bh[3]);
            }
        }
        __syncthreads();   // all pass-A reads of cur done before overwrite

        // ---- overwrite cur buffer with V_lo (plain loads; ~once per CTA) ----
#pragma unroll
        for (int it = 0; it < 8; ++it) {
            int d = ld_d + it * 32;
            uint4 w = g_xlo[(eb + (size_t)d * NN + j0g) / 8 + ld_j];
            *(uint4*)(smem + cur + d * KVSTRIDE + ld_j * 16) = w;
        }
        __syncthreads();

        // ---- GEMM2 pass B: O += P @ V_lo ----
#pragma unroll
        for (int kk = 0; kk < 8; ++kk) {
            const int j0 = kk * 16;
            uint32_t ap[4][4];
#pragma unroll
            for (int mtt = 0; mtt < 4; ++mtt)
                ldsm4(ap[mtt], pb + (uint32_t)(16 * mtt + (lane & 7) + (lane & 8)) * PSTRIDE
                                   + (uint32_t)(j0 + ((lane >> 1) & 8)) * 2);
            uint32_t blo[4];
            uint32_t off = (uint32_t)(db + (lane & 7) + ((lane >> 1) & 8)) * KVSTRIDE
                         + (uint32_t)(j0 + (lane & 8)) * 2;
            ldsm4(blo, sb + cur + off);
#pragma unroll
            for (int mtt = 0; mtt < 4; ++mtt) {
                mma16816(acc2[mtt][0], ap[mtt], blo[0], blo[1]);
                mma16816(acc2[mtt][1], ap[mtt], blo[2], blo[3]);
            }
        }
    }

    // ---- epilogue: publish 1/l, normalize, store ----
    if (nw == 0 && (lane & 3) == 0) { Invl[r0] = 1.f / l0; Invl[r1] = 1.f / l1; }
    __syncthreads();
#pragma unroll
    for (int mtt = 0; mtt < 4; ++mtt) {
        const int rr = 16 * mtt + (lane >> 2);
        const float w0 = Invl[rr];
        const float w1 = Invl[rr + 8];
#pragma unroll
        for (int h = 0; h < 2; ++h) {
            const int col = db + 8 * h + 2 * (lane & 3);
            float2 v0 = make_float2(acc2[mtt][h][0] * w0, acc2[mtt][h][1] * w0);
            float2 v1 = make_float2(acc2[mtt][h][2] * w1, acc2[mtt][h][3] * w1);
            *(float2*)(ob + (size_t)(n0 + rr) * DD + col) = v0;
            *(float2*)(ob + (size_t)(n0 + rr + 8) * DD + col) = v1;
        }
    }
}

extern "C" void kernel_launch(void* const* d_in, const int* in_sizes, int n_in,
                              void* d_out, int out_size)
{
    const float* x = (const float*)d_in[0];
    const int* beta = (n_in > 1) ? (const int*)d_in[1] : nullptr;
    float* out = (float*)d_out;

    split_bf16<<<XU4 / (512 * 2), 512>>>(x);

    cudaFuncSetAttribute(attn_hmma, cudaFuncAttributeMaxDynamicSharedMemorySize, SM_TOTAL);
    dim3 grid(NN / TM, NBL);   // 16 x 20 = 320 CTAs
    attn_hmma<<<grid, THREADS, SM_TOTAL>>>(beta, out);
}

// round 15
// speedup vs baseline: 9.7973x; 1.0124x over previous
#include <cuda_runtime.h>
#include <cuda_bf16.h>
#include <math.h>
#include <stdint.h>

#define NBL 20
#define DD  256
#define NN  1024
#define TM  64           // query rows per CTA
#define TK  128          // kv rows per tile
#define NT  (NN/TK)      // 8
#define THREADS 512
#define LOGTHR 16.118096f   // ln(1e7)

// Precomputed bf16 split of x: hi = bf16(x), lo = bf16(x - hi). 10.5 MB each.
#define XU4 (NBL*DD*NN/8)
__device__ uint4 g_xhi[XU4];
__device__ uint4 g_xlo[XU4];

// ---- smem layout (bytes); strides rotate 16B granules mod 128B (ldmatrix conflict-free)
#define SM_ALPHA 0                          // 64 fp32
#define SM_INVL  256                        // 64 fp32
#define SM_MX    512                        // [64][4] per-warp row maxes
#define SM_SX    1536                       // [64][4] per-warp row sums
#define SM_Q     2560                       // bf16 [256 d][72]  (64 used)
#define QSTRIDE  144
#define SM_KV0   (SM_Q + 256*QSTRIDE)       // bf16 [256 d][136] (128 used) buffer 0
#define KVSTRIDE 272
#define SM_KV1   (SM_KV0 + 256*KVSTRIDE)    // buffer 1
#define SM_P     (SM_KV1 + 256*KVSTRIDE)    // bf16 [64 i][136]  (128 used)
#define PSTRIDE  272
#define SM_TOTAL (SM_P + 64*PSTRIDE)        // 196096 B

__device__ __forceinline__ uint32_t smem_u32(const void* p) {
    uint32_t a;
    asm("{ .reg .u64 t; cvta.to.shared.u64 t, %1; cvt.u32.u64 %0, t; }" : "=r"(a) : "l"(p));
    return a;
}
__device__ __forceinline__ void ldsm4(uint32_t* r, uint32_t a) {
    asm volatile("ldmatrix.sync.aligned.m8n8.x4.shared.b16 {%0,%1,%2,%3}, [%4];"
                 : "=r"(r[0]), "=r"(r[1]), "=r"(r[2]), "=r"(r[3]) : "r"(a));
}
__device__ __forceinline__ void ldsm4t(uint32_t* r, uint32_t a) {
    asm volatile("ldmatrix.sync.aligned.m8n8.x4.trans.shared.b16 {%0,%1,%2,%3}, [%4];"
                 : "=r"(r[0]), "=r"(r[1]), "=r"(r[2]), "=r"(r[3]) : "r"(a));
}
__device__ __forceinline__ void mma16816(float* d, const uint32_t* a, uint32_t b0, uint32_t b1) {
    asm volatile("mma.sync.aligned.m16n8k16.row.col.f32.bf16.bf16.f32 "
                 "{%0,%1,%2,%3},{%4,%5,%6,%7},{%8,%9},{%0,%1,%2,%3};"
                 : "+f"(d[0]), "+f"(d[1]), "+f"(d[2]), "+f"(d[3])
                 : "r"(a[0]), "r"(a[1]), "r"(a[2]), "r"(a[3]), "r"(b0), "r"(b1));
}
__device__ __forceinline__ void cp_async16(uint32_t saddr, const void* gaddr) {
    asm volatile("cp.async.cg.shared.global [%0], [%1], 16;" :: "r"(saddr), "l"(gaddr) : "memory");
}
#define CP_COMMIT() asm volatile("cp.async.commit_group;" ::: "memory")
#define CP_WAIT0()  asm volatile("cp.async.wait_group 0;" ::: "memory")

// ---- kernel 1: split x into bf16 hi/lo ----
__global__ void __launch_bounds__(512, 2)
split_bf16(const float* __restrict__ x)
{
    int i0 = (blockIdx.x * 512 + threadIdx.x) * 4;
#pragma unroll
    for (int it = 0; it < 4; ++it) {
        int i = i0 + it;
        float4 v = *((const float4*)x + i);
        __nv_bfloat162 h0 = __floats2bfloat162_rn(v.x, v.y);
        __nv_bfloat162 h1 = __floats2bfloat162_rn(v.z, v.w);
        __nv_bfloat162 l0 = __floats2bfloat162_rn(v.x - __bfloat162float(h0.x),
                                                  v.y - __bfloat162float(h0.y));
        __nv_bfloat162 l1 = __floats2bfloat162_rn(v.z - __bfloat162float(h1.x),
                                                  v.w - __bfloat162float(h1.y));
        ((uint2*)g_xhi)[i] = make_uint2(*(uint32_t*)&h0, *(uint32_t*)&h1);
        ((uint2*)g_xlo)[i] = make_uint2(*(uint32_t*)&l0, *(uint32_t*)&l1);
    }
}

__global__ void __launch_bounds__(THREADS, 1)
attn_hmma(const int* __restrict__ beta_p, float* __restrict__ out)
{
    extern __shared__ char smem[];
    const uint32_t sb = smem_u32(smem);
    const int t = threadIdx.x, lane = t & 31, wid = t >> 5;
    const int mt = blockIdx.x;
    const int n0 = mt * TM;
    const int bl = blockIdx.y;
    float* __restrict__ ob = out + (size_t)bl * NN * DD;

    float betaf = 1.0f;
    if (beta_p) {
        int bbits = *beta_p;
        float bf = __int_as_float(bbits);
        betaf = (fabsf(bf) >= 1e-6f && fabsf(bf) <= 1e6f) ? bf : (float)bbits;
    }

    float* Alpha = (float*)(smem + SM_ALPHA);
    float* Invl  = (float*)(smem + SM_INVL);
    float* Mx    = (float*)(smem + SM_MX);
    float* Sx    = (float*)(smem + SM_SX);

    const size_t eb = (size_t)bl * DD * NN;
    const int ld_d = t >> 4, ld_j = t & 15;     // this thread's KV copy slice base

    const int dt = mt >> 1;                     // diagonal tile first

    // ---- prefetch tile order[0] into buffer 0 via cp.async ----
    {
        const int j0g = dt * TK;
#pragma unroll
        for (int it = 0; it < 8; ++it) {
            int d = ld_d + it * 32;
            cp_async16(sb + SM_KV0 + d * KVSTRIDE + ld_j * 16,
                       &g_xhi[(eb + (size_t)d * NN + j0g) / 8 + ld_j]);
        }
        CP_COMMIT();
    }

    // ---- Q: bf16 [d][n0..n0+63] -> smem [d][i] ----
#pragma unroll
    for (int it = 0; it < 4; ++it) {
        int idx = it * THREADS + t;
        int d = idx >> 3, ic = idx & 7;
        uint4 w = g_xhi[(eb + (size_t)d * NN + n0) / 8 + ic];
        *(uint4*)(smem + SM_Q + d * QSTRIDE + ic * 16) = w;
    }

    float acc2[4][2][4];
#pragma unroll
    for (int a = 0; a < 4; ++a)
#pragma unroll
        for (int b = 0; b < 2; ++b)
#pragma unroll
            for (int c = 0; c < 4; ++c) acc2[a][b][c] = 0.f;

    const int mw = wid & 3, nw = wid >> 2;
    const int i0 = mw * 16, jb = nw * 32;
    const int db = wid * 16;
    const int r0 = i0 + (lane >> 2), r1 = r0 + 8;

    // precomputed intra-fragment offsets (invariant over k)
    const uint32_t aoff = (uint32_t)((lane & 7) + ((lane >> 1) & 8)) * QSTRIDE
                        + (uint32_t)(i0 + (lane & 8)) * 2;
    const uint32_t boff0 = (uint32_t)((lane & 7) + (lane & 8)) * KVSTRIDE
                         + (uint32_t)(jb + ((lane >> 1) & 8)) * 2;
    const uint32_t boff1 = boff0 + 32;   // +16 bf16 cols

    float m0 = -1e30f, m1 = -1e30f;
    float l0 = 0.f, l1 = 0.f;

    for (int idx8 = 0; idx8 < NT; ++idx8) {
        const int cur = (idx8 & 1) ? SM_KV1 : SM_KV0;
        const int nxt = (idx8 & 1) ? SM_KV0 : SM_KV1;

        CP_WAIT0();           // current tile's async copies landed (this thread)
        __syncthreads();      // ... and everyone else's; prior readers of `nxt` done

        // ---- issue prefetch of the next tile into the other buffer ----
        if (idx8 + 1 < NT) {
            const int ktn = (idx8 + 1 <= dt) ? idx8 : idx8 + 1;
            const int j0n = ktn * TK;
#pragma unroll
            for (int it = 0; it < 8; ++it) {
                int d = ld_d + it * 32;
                cp_async16(sb + nxt + d * KVSTRIDE + ld_j * 16,
                           &g_xhi[(eb + (size_t)d * NN + j0n) / 8 + ld_j]);
            }
            CP_COMMIT();
        }

        // ---- GEMM1 (software-pipelined fragments): S = Q @ K^T, warp 16x32 ----
        float acc1[4][4];
#pragma unroll
        for (int n = 0; n < 4; ++n)
#pragma unroll
            for (int c = 0; c < 4; ++c) acc1[n][c] = 0.f;
        {
            const uint32_t qa = sb + SM_Q + aoff;
            const uint32_t kb0 = sb + cur + boff0;
            const uint32_t kb1 = sb + cur + boff1;
            uint32_t afr[2][4], bfr[2][2][4];
            // prologue: load k=0 fragments
            ldsm4t(afr[0], qa);
            ldsm4t(bfr[0][0], kb0);
            ldsm4t(bfr[0][1], kb1);
#pragma unroll
            for (int k = 0; k < 16; ++k) {
                const int cb = k & 1, pb2 = cb ^ 1;
                if (k + 1 < 16) {   // prefetch k+1 fragments before using k's
                    const uint32_t dof = (uint32_t)((k + 1) * 16);
                    ldsm4t(afr[pb2], qa + dof * QSTRIDE);
                    ldsm4t(bfr[pb2][0], kb0 + dof * KVSTRIDE);
                    ldsm4t(bfr[pb2][1], kb1 + dof * KVSTRIDE);
                }
                mma16816(acc1[0], afr[cb], bfr[cb][0][0], bfr[cb][0][1]);
                mma16816(acc1[1], afr[cb], bfr[cb][0][2], bfr[cb][0][3]);
                mma16816(acc1[2], afr[cb], bfr[cb][1][0], bfr[cb][1][1]);
                mma16816(acc1[3], afr[cb], bfr[cb][1][2], bfr[cb][1][3]);
            }
        }

        // ---- warp-partial row maxes of beta*S ----
        float wm0 = -1e30f, wm1 = -1e30f;
#pragma unroll
        for (int n = 0; n < 4; ++n) {
            wm0 = fmaxf(wm0, fmaxf(betaf * acc1[n][0], betaf * acc1[n][1]));
            wm1 = fmaxf(wm1, fmaxf(betaf * acc1[n][2], betaf * acc1[n][3]));
        }
        wm0 = fmaxf(wm0, __shfl_xor_sync(0xffffffffu, wm0, 1));
        wm0 = fmaxf(wm0, __shfl_xor_sync(0xffffffffu, wm0, 2));
        wm1 = fmaxf(wm1, __shfl_xor_sync(0xffffffffu, wm1, 1));
        wm1 = fmaxf(wm1, __shfl_xor_sync(0xffffffffu, wm1, 2));

        int need = __syncthreads_or((wm0 > m0 - LOGTHR) || (wm1 > m1 - LOGTHR));
        if (!need) continue;   // tile certified negligible (all p < 1e-7)

        // ---- executed tile: cross-warp max ----
        if ((lane & 3) == 0) { Mx[r0 * 4 + nw] = wm0; Mx[r1 * 4 + nw] = wm1; }
        __syncthreads();
        float4 q0 = *(const float4*)(Mx + r0 * 4);
        float4 q1 = *(const float4*)(Mx + r1 * 4);
        float t0 = fmaxf(fmaxf(q0.x, q0.y), fmaxf(q0.z, q0.w));
        float t1 = fmaxf(fmaxf(q1.x, q1.y), fmaxf(q1.z, q1.w));
        float n_m0 = fmaxf(m0, t0), n_m1 = fmaxf(m1, t1);
        float al0 = __expf(m0 - n_m0), al1 = __expf(m1 - n_m1);

        float ws0 = 0.f, ws1 = 0.f;
#pragma unroll
        for (int n = 0; n < 4; ++n) {
            float p00 = __expf(betaf * acc1[n][0] - n_m0);
            float p01 = __expf(betaf * acc1[n][1] - n_m0);
            float p10 = __expf(betaf * acc1[n][2] - n_m1);
            float p11 = __expf(betaf * acc1[n][3] - n_m1);
            ws0 += p00 + p01; ws1 += p10 + p11;
            __nv_bfloat162 v0 = __floats2bfloat162_rn(p00, p01);
            __nv_bfloat162 v1 = __floats2bfloat162_rn(p10, p11);
            int col = jb + n * 8 + 2 * (lane & 3);
            *(uint32_t*)(smem + SM_P + r0 * PSTRIDE + col * 2) = *(uint32_t*)&v0;
            *(uint32_t*)(smem + SM_P + r1 * PSTRIDE + col * 2) = *(uint32_t*)&v1;
        }
        ws0 += __shfl_xor_sync(0xffffffffu, ws0, 1);
        ws0 += __shfl_xor_sync(0xffffffffu, ws0, 2);
        ws1 += __shfl_xor_sync(0xffffffffu, ws1, 1);
        ws1 += __shfl_xor_sync(0xffffffffu, ws1, 2);
        if ((lane & 3) == 0) {
            Sx[r0 * 4 + nw] = ws0; Sx[r1 * 4 + nw] = ws1;
            if (nw == 0) { Alpha[r0] = al0; Alpha[r1] = al1; }
        }
        __syncthreads();   // P, Sx, Alpha visible

        float4 s0 = *(const float4*)(Sx + r0 * 4);
        float4 s1 = *(const float4*)(Sx + r1 * 4);
        l0 = l0 * al0 + (s0.x + s0.y) + (s0.z + s0.w);
        l1 = l1 * al1 + (s1.x + s1.y) + (s1.z + s1.w);
        m0 = n_m0; m1 = n_m1;

        if (idx8 > 0) {
#pragma unroll
            for (int mtt = 0; mtt < 4; ++mtt) {
                float a0 = Alpha[16 * mtt + (lane >> 2)];
                float a1 = Alpha[16 * mtt + (lane >> 2) + 8];
#pragma unroll
                for (int h = 0; h < 2; ++h) {
                    acc2[mtt][h][0] *= a0; acc2[mtt][h][1] *= a0;
                    acc2[mtt][h][2] *= a1; acc2[mtt][h][3] *= a1;
                }
            }
        }

        // ---- GEMM2 pass A: O += P @ V_hi (from cur buffer) ----
        const int j0g = ((idx8 == 0) ? dt : (idx8 <= dt ? idx8 - 1 : idx8)) * TK;
        const uint32_t pbs = sb + SM_P;
#pragma unroll
        for (int kk = 0; kk < 8; ++kk) {
            const int j0 = kk * 16;
            uint32_t ap[4][4];
#pragma unroll
            for (int mtt = 0; mtt < 4; ++mtt)
                ldsm4(ap[mtt], pbs + (uint32_t)(16 * mtt + (lane & 7) + (lane & 8)) * PSTRIDE
                                   + (uint32_t)(j0 + ((lane >> 1) & 8)) * 2);
            uint32_t bh[4];
            uint32_t off = (uint32_t)(db + (lane & 7) + ((lane >> 1) & 8)) * KVSTRIDE
                         + (uint32_t)(j0 + (lane & 8)) * 2;
            ldsm4(bh, sb + cur + off);
#pragma unroll
            for (int mtt = 0; mtt < 4; ++mtt) {
                mma16816(acc2[mtt][0], ap[mtt], bh[0], bh[1]);
                mma16816(acc2[mtt][1], ap[mtt], bh[2], bh[3]);
            }
        }
        __syncthreads();   // all pass-A reads of cur done before overwrite

        // ---- overwrite cur buffer with V_lo (plain loads; ~once per CTA) ----
#pragma unroll
        for (int it = 0; it < 8; ++it) {
            int d = ld_d + it * 32;
            uint4 w = g_xlo[(eb + (size_t)d * NN + j0g) / 8 + ld_j];
            *(uint4*)(smem + cur + d * KVSTRIDE + ld_j * 16) = w;
        }
        __syncthreads();

        // ---- GEMM2 pass B: O += P @ V_lo ----
#pragma unroll
        for (int kk = 0; kk < 8; ++kk) {
            const int j0 = kk * 16;
            uint32_t ap[4][4];
#pragma unroll
            for (int mtt = 0; mtt < 4; ++mtt)
                ldsm4(ap[mtt], pbs + (uint32_t)(16 * mtt + (lane & 7) + (lane & 8)) * PSTRIDE
                                   + (uint32_t)(j0 + ((lane >> 1) & 8)) * 2);
            uint32_t blo[4];
            uint32_t off = (uint32_t)(db + (lane & 7) + ((lane >> 1) & 8)) * KVSTRIDE
                         + (uint32_t)(j0 + (lane & 8)) * 2;
            ldsm4(blo, sb + cur + off);
#pragma unroll
            for (int mtt = 0; mtt < 4; ++mtt) {
                mma16816(acc2[mtt][0], ap[mtt], blo[0], blo[1]);
                mma16816(acc2[mtt][1], ap[mtt], blo[2], blo[3]);
            }
        }
    }

    // ---- epilogue: publish 1/l, normalize, store ----
    if (nw == 0 && (lane & 3) == 0) { Invl[r0] = 1.f / l0; Invl[r1] = 1.f / l1; }
    __syncthreads();
#pragma unroll
    for (int mtt = 0; mtt < 4; ++mtt) {
        const int rr = 16 * mtt + (lane >> 2);
        const float w0 = Invl[rr];
        const float w1 = Invl[rr + 8];
#pragma unroll
        for (int h = 0; h < 2; ++h) {
            const int col = db + 8 * h + 2 * (lane & 3);
            float2 v0 = make_float2(acc2[mtt][h][0] * w0, acc2[mtt][h][1] * w0);
            float2 v1 = make_float2(acc2[mtt][h][2] * w1, acc2[mtt][h][3] * w1);
            *(float2*)(ob + (size_t)(n0 + rr) * DD + col) = v0;
            *(float2*)(ob + (size_t)(n0 + rr + 8) * DD + col) = v1;
        }
    }
}

extern "C" void kernel_launch(void* const* d_in, const int* in_sizes, int n_in,
                              void* d_out, int out_size)
{
    const float* x = (const float*)d_in[0];
    const int* beta = (n_in > 1) ? (const int*)d_in[1] : nullptr;
    float* out = (float*)d_out;

    split_bf16<<<XU4 / (512 * 2), 512>>>(x);

    cudaFuncSetAttribute(attn_hmma, cudaFuncAttributeMaxDynamicSharedMemorySize, SM_TOTAL);
    dim3 grid(NN / TM, NBL);   // 16 x 20 = 320 CTAs
    attn_hmma<<<grid, THREADS, SM_TOTAL>>>(beta, out);
}